// round 10
// baseline (speedup 1.0000x reference)
#include <cuda_runtime.h>
#include <cuda_fp16.h>
#include <cstdint>
#include <cstddef>

typedef __half hf;

// ---------------- tile constants ----------------
#define TM    64
#define ROWB  144
#define OFF_A  0
#define OFF_B  9216
#define STAGE  18432
#define NSTG   6
#define SMEM_SZ (NSTG * STAGE)    // 110592 B
#define NCTA  128
#define HB    131072              // 64*2048 elems

// ---------------- asm helpers ----------------
__device__ __forceinline__ void cpa(uint32_t d, const void* s) {
    asm volatile("cp.async.cg.shared.global [%0], [%1], 16;" :: "r"(d), "l"(s));
}
__device__ __forceinline__ void cpcommit() {
    asm volatile("cp.async.commit_group;" ::: "memory");
}
template <int N> __device__ __forceinline__ void cpwait() {
    asm volatile("cp.async.wait_group %0;" :: "n"(N) : "memory");
}
#define LDSM4(R, addr) \
    asm volatile("ldmatrix.sync.aligned.m8n8.x4.shared.b16 {%0,%1,%2,%3}, [%4];" \
        : "=r"((R)[0]), "=r"((R)[1]), "=r"((R)[2]), "=r"((R)[3]) : "r"(addr))
#define MMA(D, A, b0, b1) \
    asm volatile("mma.sync.aligned.m16n8k16.row.col.f32.f16.f16.f32 " \
        "{%0,%1,%2,%3}, {%4,%5,%6,%7}, {%8,%9}, {%0,%1,%2,%3};" \
        : "+f"((D)[0]), "+f"((D)[1]), "+f"((D)[2]), "+f"((D)[3]) \
        : "r"((A)[0]), "r"((A)[1]), "r"((A)[2]), "r"((A)[3]), "r"(b0), "r"(b1))

// ---------------- scratch ----------------
#define LWF 16777216               // 8192*2048
#define WCATN 33554432             // 8192*4096
__device__ hf g_wcat[5 * WCATN];                     // enc l1,l2; dec l0,l1,l2
__device__ hf g_ewhh0[LWF];                          // enc l0 Whh (interleaved)
__device__ hf g_ewih0[LWF];                          // enc l0 Wih (flat)
__device__ hf g_fc1w[4194304], g_fc2w[2097152];
__device__ hf g_fd1w[2097152], g_fd2w[4194304];
__device__ hf g_xh[4194304];                         // [1024,4096]
__device__ hf g_f1a[1048576];                        // [1024,1024]
__device__ hf g_f2a[2097152];                        // [1024,2048]
__device__ hf g_d1a[2 * 65536];                      // ping-pong [64,1024]
__device__ hf g_hH[6 * HB];                          // [layer][parity]
__device__ float g_pre[16 * 524288];
__device__ float g_c[3 * HB];
__device__ unsigned g_bar[2];

// ===========================================================================
// prepass kernels
// ===========================================================================
struct SplitArgs {
    const float* s[6];
    hf* h[6];
    long off4[7];
};

__global__ void __launch_bounds__(256) split_all(SplitArgs a)
{
    const long total = a.off4[6];
    for (long v = (long)blockIdx.x * 256 + threadIdx.x; v < total;
         v += (long)gridDim.x * 256) {
        int seg = 0;
#pragma unroll
        for (int i = 0; i < 5; i++) seg += (v >= a.off4[i + 1]) ? 1 : 0;
        long e = (v - a.off4[seg]) * 4;
        float4 x = *(const float4*)(a.s[seg] + e);
        hf h0 = __float2half_rn(x.x), h1 = __float2half_rn(x.y);
        hf h2 = __float2half_rn(x.z), h3 = __float2half_rn(x.w);
        uint2 ph;
        ph.x = (uint32_t)*(uint16_t*)&h0 | ((uint32_t)*(uint16_t*)&h1 << 16);
        ph.y = (uint32_t)*(uint16_t*)&h2 | ((uint32_t)*(uint16_t*)&h3 << 16);
        *(uint2*)(a.h[seg] + e) = ph;
    }
}

__global__ void __launch_bounds__(256) lstm_pack(
    const float* __restrict__ wih, const float* __restrict__ whh,
    hf* __restrict__ dst, int hasx)
{
    const int K = hasx ? 4096 : 2048;
    const long total = (long)8192 * K / 4;
    for (long v = (long)blockIdx.x * 256 + threadIdx.x; v < total;
         v += (long)gridDim.x * 256) {
        int r = (int)(v / (K >> 2));
        int c = (int)(v % (K >> 2)) * 4;
        int gate = (r >> 4) & 3, jblk = r >> 6, jin = r & 15;
        int orig = gate * 2048 + jblk * 16 + jin;
        const float* src = (c < 2048 || !hasx)
            ? (hasx ? wih : whh) + (size_t)orig * 2048 + (c & 2047)
            : whh + (size_t)orig * 2048 + (c - 2048);
        float4 x = *(const float4*)src;
        hf h0 = __float2half_rn(x.x), h1 = __float2half_rn(x.y);
        hf h2 = __float2half_rn(x.z), h3 = __float2half_rn(x.w);
        uint2 ph;
        ph.x = (uint32_t)*(uint16_t*)&h0 | ((uint32_t)*(uint16_t*)&h1 << 16);
        ph.y = (uint32_t)*(uint16_t*)&h2 | ((uint32_t)*(uint16_t*)&h3 << 16);
        *(uint2*)(dst + (size_t)r * K + c) = ph;
    }
}

// ===========================================================================
// shared 1-term GEMM mainloop: D[64f x 64b] = W[64,K] * B^T over [x | h]
// ===========================================================================
__device__ __forceinline__ void run_gemm(
    const hf* __restrict__ W, int K,
    const hf* __restrict__ Bx, int Kx, int ldbx,
    const hf* __restrict__ Bh, int ldbh,
    uint32_t sb, float acc[2][2][4])
{
    const int t = threadIdx.x;
    const int NC = K >> 6;
    const int r0 = t >> 3, seg = t & 7;
    __syncthreads();     // previous phase's smem use complete
    auto issue = [&](int chunk) {
        if (chunk < NC) {
            const uint32_t st = sb + (chunk % NSTG) * STAGE;
            const int kg = chunk << 6;
            const hf* b; int ks, ldb;
            if (kg < Kx) { b = Bx; ks = kg; ldb = ldbx; }
            else         { b = Bh; ks = kg - Kx; ldb = ldbh; }
#pragma unroll
            for (int i = 0; i < 2; i++) {
                int row = r0 + i * 32;
                uint32_t dd = st + row * ROWB + seg * 16;
                cpa(dd + OFF_A, W + (size_t)row * K   + kg + seg * 8);
                cpa(dd + OFF_B, b + (size_t)row * ldb + ks + seg * 8);
            }
        }
        cpcommit();
    };
    issue(0); issue(1); issue(2); issue(3); issue(4);

    const int w = t >> 5, lane = t & 31;
    const int moff = (w & 1) * 32, noff = (w >> 1) * 16;
    const int arow = lane & 15, ahalf = lane >> 4;
    const int bj = lane >> 3;
    const int brow = ((bj >> 1) * 8) + (lane & 7), bkh = bj & 1;

#pragma unroll
    for (int mi = 0; mi < 2; mi++)
#pragma unroll
        for (int nj = 0; nj < 2; nj++)
#pragma unroll
            for (int q = 0; q < 4; q++) acc[mi][nj][q] = 0.f;

    for (int s = 0; s < NC; s++) {
        cpwait<4>();
        __syncthreads();
        const uint32_t st = sb + (s % NSTG) * STAGE;
#pragma unroll
        for (int k16 = 0; k16 < 4; k16++) {
            const int kb = k16 * 32;
            uint32_t ah[2][4], bb[4];
#pragma unroll
            for (int mi = 0; mi < 2; mi++) {
                uint32_t ra = (uint32_t)((moff + mi * 16 + arow) * ROWB + kb + ahalf * 16);
                LDSM4(ah[mi], st + OFF_A + ra);
            }
            uint32_t rb = (uint32_t)((noff + brow) * ROWB + kb + bkh * 16);
            LDSM4(bb, st + OFF_B + rb);
#pragma unroll
            for (int mi = 0; mi < 2; mi++)
#pragma unroll
                for (int nj = 0; nj < 2; nj++)
                    MMA(acc[mi][nj], ah[mi], bb[nj * 2], bb[nj * 2 + 1]);
        }
        issue(s + 5);
    }
}

__device__ __forceinline__ void stage_cs(float acc[2][2][4], float* cs)
{
    const int t = threadIdx.x;
    const int w = t >> 5, lane = t & 31;
    const int moff = (w & 1) * 32, noff = (w >> 1) * 16;
    const int rr = lane >> 2, cc = (lane & 3) * 2;
    __syncthreads();
#pragma unroll
    for (int mi = 0; mi < 2; mi++)
#pragma unroll
        for (int nj = 0; nj < 2; nj++) {
            int m = moff + mi * 16 + rr;
            int n = noff + nj * 8 + cc;
            cs[n * 68 + m]           = acc[mi][nj][0];
            cs[(n + 1) * 68 + m]     = acc[mi][nj][1];
            cs[n * 68 + m + 8]       = acc[mi][nj][2];
            cs[(n + 1) * 68 + m + 8] = acc[mi][nj][3];
        }
    __syncthreads();
}

__device__ __forceinline__ void gbar(unsigned* cnt, unsigned* gen, unsigned& mygen)
{
    __threadfence();
    __syncthreads();
    if (threadIdx.x == 0) {
        mygen += 1;
        unsigned prev = atomicAdd(cnt, 1u);
        if (prev == NCTA - 1) {
            atomicExch(cnt, 0u);
            __threadfence();
            atomicExch(gen, mygen);
        } else {
            while (atomicAdd(gen, 0u) < mygen) __nanosleep(64);
            __threadfence();
        }
    }
    __syncthreads();
}

// ===========================================================================
// batched FC GEMM (prepass-stage)
// dual=2: f-major fp32 store to outf + y*524288 ; else relu -> fp16
// ===========================================================================
__global__ void __launch_bounds__(256, 2)
gemm_ms(const hf* __restrict__ A0, const hf* __restrict__ B0,
        const float* __restrict__ bias,
        float* __restrict__ outf, hf* __restrict__ outh,
        int K, int ldc, int dual)
{
    extern __shared__ char smem[];
    const uint32_t sb = (uint32_t)__cvta_generic_to_shared(smem);
    const int t = threadIdx.x;
    const int fbase = blockIdx.x * TM;
    const int nbase = blockIdx.y * 64;

    float acc[2][2][4];
    run_gemm(A0 + (size_t)fbase * K, K,
             B0 + (size_t)nbase * K, K, K,
             nullptr, 0, sb, acc);

    const int w = t >> 5, lane = t & 31;
    const int moff = (w & 1) * 32, noff = (w >> 1) * 16;
    const int rr = lane >> 2, cc = (lane & 3) * 2;

    if (dual == 2) {
        float* po = outf + (size_t)blockIdx.y * 524288;
#pragma unroll
        for (int mi = 0; mi < 2; mi++)
#pragma unroll
            for (int nj = 0; nj < 2; nj++) {
                int m = moff + mi * 16 + rr;
                int n = noff + nj * 8 + cc;
                *(float2*)(po + (size_t)(fbase + m) * 64 + n) =
                    make_float2(acc[mi][nj][0], acc[mi][nj][1]);
                *(float2*)(po + (size_t)(fbase + m + 8) * 64 + n) =
                    make_float2(acc[mi][nj][2], acc[mi][nj][3]);
            }
        return;
    }

    float* cs = (float*)smem;
    stage_cs(acc, cs);
    const int b = t >> 2, j0 = (t & 3) * 16;
    const float* bp = bias + fbase + j0;
    hf* dh = outh + (size_t)(nbase + b) * ldc + fbase + j0;
#pragma unroll
    for (int j = 0; j < 16; j++) {
        float v = fmaxf(cs[b * 68 + j0 + j] + bp[j], 0.f);
        dh[j] = __float2half_rn(v);
    }
}

// ===========================================================================
// persistent kernels
// ===========================================================================
struct PP {
    const hf *wcat, *ewhh0;
    const float *pre, *en_b, *de_b;
    hf *hH;
    float *c;
    const hf *fd1w, *fd2w;
    const float *fd1b, *fd2b;
    hf *d1a;
    float *out;
    unsigned *bar;
};

__device__ __forceinline__ void lstm_cell_epi(
    float acc[2][2][4], float* cs, const float* pre, const float* bias,
    float* c, hf* hh, int jg0)
{
    stage_cs(acc, cs);
    const int t = threadIdx.x;
    const int b = t >> 2, j4 = (t & 3) * 4;
    float4 cold = *(const float4*)(c + (size_t)b * 2048 + jg0 + j4);
    float cn[4]; hf hi4[4];
#pragma unroll
    for (int q = 0; q < 4; q++) {
        const int j = j4 + q, jg = jg0 + j;
        float iv = cs[b * 68 + j];
        float fv = cs[b * 68 + 16 + j];
        float gv = cs[b * 68 + 32 + j];
        float ov = cs[b * 68 + 48 + j];
        if (pre) {
            iv += pre[(size_t)(jg) * 64 + b];
            fv += pre[(size_t)(2048 + jg) * 64 + b];
            gv += pre[(size_t)(4096 + jg) * 64 + b];
            ov += pre[(size_t)(6144 + jg) * 64 + b];
        }
        iv += bias[jg]; fv += bias[2048 + jg];
        gv += bias[4096 + jg]; ov += bias[6144 + jg];
        float si = 1.f / (1.f + __expf(-iv));
        float sf = 1.f / (1.f + __expf(-fv));
        float so = 1.f / (1.f + __expf(-ov));
        float c2 = sf * (&cold.x)[q] + si * tanhf(gv);
        float h2 = so * tanhf(c2);
        cn[q] = c2;
        hi4[q] = __float2half_rn(h2);
    }
    *(float4*)(c + (size_t)b * 2048 + jg0 + j4) = *(float4*)cn;
    *(uint2*)(hh + (size_t)b * 2048 + jg0 + j4) = *(uint2*)hi4;
}

__global__ void __launch_bounds__(256)
enc_persist(PP p)
{
    extern __shared__ char smem[];
    const uint32_t sb = (uint32_t)__cvta_generic_to_shared(smem);
    float* cs = (float*)smem;
    const int bid = blockIdx.x;
    const int fbase = bid * TM, jg0 = bid * 16;
    unsigned mygen = 0;
    float acc[2][2][4];
    auto HHp = [&](int l, int pr) { return p.hH + (size_t)(l * 2 + pr) * HB; };

    for (int t16 = 0; t16 < 16; t16++) {
        const int rp = t16 & 1, wp = 1 - rp;
        run_gemm(p.ewhh0 + (size_t)fbase * 2048, 2048,
                 nullptr, 0, 0, HHp(0, rp), 2048, sb, acc);
        lstm_cell_epi(acc, cs, p.pre + (size_t)t16 * 524288, p.en_b,
                      p.c, HHp(0, wp), jg0);
        gbar(p.bar, p.bar + 1, mygen);
        run_gemm(p.wcat + (size_t)0 * WCATN + (size_t)fbase * 4096, 4096,
                 HHp(0, wp), 2048, 2048, HHp(1, rp), 2048, sb, acc);
        lstm_cell_epi(acc, cs, nullptr, p.en_b + 8192,
                      p.c + HB, HHp(1, wp), jg0);
        gbar(p.bar, p.bar + 1, mygen);
        run_gemm(p.wcat + (size_t)1 * WCATN + (size_t)fbase * 4096, 4096,
                 HHp(1, wp), 2048, 2048, HHp(2, rp), 2048, sb, acc);
        lstm_cell_epi(acc, cs, nullptr, p.en_b + 16384,
                      p.c + 2 * HB, HHp(2, wp), jg0);
        gbar(p.bar, p.bar + 1, mygen);
    }
}

__global__ void __launch_bounds__(256)
dec_persist(PP p)
{
    extern __shared__ char smem[];
    const uint32_t sb = (uint32_t)__cvta_generic_to_shared(smem);
    float* cs = (float*)smem;
    const int bid = blockIdx.x;
    const int fbase = bid * TM, jg0 = bid * 16;
    unsigned mygen = 0;
    float acc[2][2][4];
    auto HHp = [&](int l, int pr) { return p.hH + (size_t)(l * 2 + pr) * HB; };

    for (int t16 = 0; t16 < 16; t16++) {
        const int rp = t16 & 1, wp = 1 - rp;
        run_gemm(p.wcat + (size_t)2 * WCATN + (size_t)fbase * 4096, 4096,
                 HHp(2, rp), 2048, 2048, HHp(0, rp), 2048, sb, acc);
        lstm_cell_epi(acc, cs, nullptr, p.de_b, p.c, HHp(0, wp), jg0);
        gbar(p.bar, p.bar + 1, mygen);
        run_gemm(p.wcat + (size_t)3 * WCATN + (size_t)fbase * 4096, 4096,
                 HHp(0, wp), 2048, 2048, HHp(1, rp), 2048, sb, acc);
        lstm_cell_epi(acc, cs, nullptr, p.de_b + 8192,
                      p.c + HB, HHp(1, wp), jg0);
        gbar(p.bar, p.bar + 1, mygen);
        run_gemm(p.wcat + (size_t)4 * WCATN + (size_t)fbase * 4096, 4096,
                 HHp(1, wp), 2048, 2048, HHp(2, rp), 2048, sb, acc);
        lstm_cell_epi(acc, cs, nullptr, p.de_b + 16384,
                      p.c + 2 * HB, HHp(2, wp), jg0);
        gbar(p.bar, p.bar + 1, mygen);
        // head phase: fd1(t) on CTAs 0..15  ||  fd2(t-1) on CTAs 64..127
        if (bid < 16) {
            run_gemm(p.fd1w + (size_t)fbase * 2048, 2048,
                     HHp(2, wp), 2048, 2048, nullptr, 0, sb, acc);
            stage_cs(acc, cs);
            const int t = threadIdx.x;
            const int b = t >> 2, j0 = (t & 3) * 16;
            const float* bp = p.fd1b + fbase + j0;
            hf* dh = p.d1a + (size_t)(t16 & 1) * 65536 + (size_t)b * 1024 + fbase + j0;
#pragma unroll
            for (int j = 0; j < 16; j++) {
                float v = fmaxf(cs[b * 68 + j0 + j] + bp[j], 0.f);
                dh[j] = __float2half_rn(v);
            }
        } else if (bid >= 64 && t16 > 0) {
            const int f2 = (bid - 64) * TM;
            run_gemm(p.fd2w + (size_t)f2 * 1024, 1024,
                     p.d1a + (size_t)((t16 - 1) & 1) * 65536, 1024, 1024,
                     nullptr, 0, sb, acc);
            stage_cs(acc, cs);
            const int t = threadIdx.x;
            const int b = t >> 2, j0 = (t & 3) * 16;
            const float* bp = p.fd2b + f2 + j0;
            float* dst = p.out + (size_t)(t16 - 1) * 262144 + (size_t)b * 4096 + f2 + j0;
#pragma unroll
            for (int j = 0; j < 16; j++) {
                float v = cs[b * 68 + j0 + j] + bp[j];
                dst[j] = 1.f / (1.f + __expf(-v));
            }
        }
        gbar(p.bar, p.bar + 1, mygen);
    }
    // final fd2(15) on CTAs 64..127
    if (bid >= 64) {
        const int f2 = (bid - 64) * TM;
        run_gemm(p.fd2w + (size_t)f2 * 1024, 1024,
                 p.d1a + 65536, 1024, 1024, nullptr, 0, sb, acc);
        stage_cs(acc, cs);
        const int t = threadIdx.x;
        const int b = t >> 2, j0 = (t & 3) * 16;
        const float* bp = p.fd2b + f2 + j0;
        float* dst = p.out + (size_t)15 * 262144 + (size_t)b * 4096 + f2 + j0;
#pragma unroll
        for (int j = 0; j < 16; j++) {
            float v = cs[b * 68 + j0 + j] + bp[j];
            dst[j] = 1.f / (1.f + __expf(-v));
        }
    }
}

extern "C" void kernel_launch(void* const* d_in, const int* in_sizes, int n_in,
                              void* d_out, int out_size)
{
    const float* x        = (const float*)d_in[0];
    const float* fc_en1_w = (const float*)d_in[1];
    const float* fc_en1_b = (const float*)d_in[2];
    const float* fc_en2_w = (const float*)d_in[3];
    const float* fc_en2_b = (const float*)d_in[4];
    const float* en_wih   = (const float*)d_in[5];
    const float* en_whh   = (const float*)d_in[6];
    const float* en_b     = (const float*)d_in[7];
    const float* de_wih   = (const float*)d_in[8];
    const float* de_whh   = (const float*)d_in[9];
    const float* de_b     = (const float*)d_in[10];
    const float* fc_de1_w = (const float*)d_in[11];
    const float* fc_de1_b = (const float*)d_in[12];
    const float* fc_de2_w = (const float*)d_in[13];
    const float* fc_de2_b = (const float*)d_in[14];
    float* out = (float*)d_out;

    hf *wcat, *ewhh0, *ewih0, *fc1w, *fc2w, *fd1w, *fd2w;
    hf *xh, *f1a, *f2a, *d1a, *hH;
    float *pre, *c;
    unsigned* bar;
    cudaGetSymbolAddress((void**)&wcat, g_wcat);
    cudaGetSymbolAddress((void**)&ewhh0, g_ewhh0);
    cudaGetSymbolAddress((void**)&ewih0, g_ewih0);
    cudaGetSymbolAddress((void**)&fc1w, g_fc1w);  cudaGetSymbolAddress((void**)&fc2w, g_fc2w);
    cudaGetSymbolAddress((void**)&fd1w, g_fd1w);  cudaGetSymbolAddress((void**)&fd2w, g_fd2w);
    cudaGetSymbolAddress((void**)&xh, g_xh);
    cudaGetSymbolAddress((void**)&f1a, g_f1a);    cudaGetSymbolAddress((void**)&f2a, g_f2a);
    cudaGetSymbolAddress((void**)&d1a, g_d1a);    cudaGetSymbolAddress((void**)&hH, g_hH);
    cudaGetSymbolAddress((void**)&pre, g_pre);    cudaGetSymbolAddress((void**)&c, g_c);
    cudaGetSymbolAddress((void**)&bar, g_bar);

    cudaFuncSetAttribute(gemm_ms,     cudaFuncAttributeMaxDynamicSharedMemorySize, SMEM_SZ);
    cudaFuncSetAttribute(enc_persist, cudaFuncAttributeMaxDynamicSharedMemorySize, SMEM_SZ);
    cudaFuncSetAttribute(dec_persist, cudaFuncAttributeMaxDynamicSharedMemorySize, SMEM_SZ);

    auto HHp = [&](int l, int pr) { return hH + (size_t)(l * 2 + pr) * HB; };

    // ---- prepass ----
    {
        SplitArgs a;
        const float* srcs[6] = {en_wih, fc_en1_w, fc_en2_w, fc_de1_w, fc_de2_w, x};
        hf* hs[6] = {ewih0, fc1w, fc2w, fd1w, fd2w, xh};
        long ns[6] = {LWF, 4194304, 2097152, 2097152, 4194304, 4194304};
        long acc = 0;
        for (int i = 0; i < 6; i++) {
            a.s[i] = srcs[i]; a.h[i] = hs[i];
            a.off4[i] = acc; acc += ns[i] / 4;
        }
        a.off4[6] = acc;
        split_all<<<1024, 256>>>(a);
    }
    lstm_pack<<<2048, 256>>>(en_wih + (size_t)1 * LWF, en_whh + (size_t)1 * LWF,
                             wcat + (size_t)0 * WCATN, 1);
    lstm_pack<<<2048, 256>>>(en_wih + (size_t)2 * LWF, en_whh + (size_t)2 * LWF,
                             wcat + (size_t)1 * WCATN, 1);
    lstm_pack<<<2048, 256>>>(de_wih,                   de_whh,
                             wcat + (size_t)2 * WCATN, 1);
    lstm_pack<<<2048, 256>>>(de_wih + (size_t)1 * LWF, de_whh + (size_t)1 * LWF,
                             wcat + (size_t)3 * WCATN, 1);
    lstm_pack<<<2048, 256>>>(de_wih + (size_t)2 * LWF, de_whh + (size_t)2 * LWF,
                             wcat + (size_t)4 * WCATN, 1);
    lstm_pack<<<1024, 256>>>(nullptr, en_whh, ewhh0, 0);

    cudaMemsetAsync(hH, 0, 6 * HB * sizeof(hf));
    cudaMemsetAsync(c,  0, 3 * HB * sizeof(float));

    // ---- batched encoder FCs + l0 pre-gates ----
    gemm_ms<<<dim3(16, 16), 256, SMEM_SZ>>>(fc1w, xh, fc_en1_b,
        nullptr, f1a, 4096, 1024, 0);
    gemm_ms<<<dim3(32, 16), 256, SMEM_SZ>>>(fc2w, f1a, fc_en2_b,
        nullptr, f2a, 1024, 2048, 0);
    gemm_ms<<<dim3(128, 16), 256, SMEM_SZ>>>(ewih0, f2a, nullptr,
        pre, nullptr, 2048, 0, 2);

    PP p;
    p.wcat = wcat; p.ewhh0 = ewhh0; p.pre = pre;
    p.en_b = en_b; p.de_b = de_b;
    p.hH = hH; p.c = c;
    p.fd1w = fd1w; p.fd2w = fd2w; p.fd1b = fc_de1_b; p.fd2b = fc_de2_b;
    p.d1a = d1a; p.out = out; p.bar = bar;

    // ---- encoder ----
    cudaMemsetAsync(bar, 0, 2 * sizeof(unsigned));
    enc_persist<<<NCTA, 256, SMEM_SZ>>>(p);

    // ---- decoder init: h0(p0) = enc h2(p0); h1,h2(p0) zero; c zero ----
    cudaMemcpyAsync(HHp(0, 0), HHp(2, 0), HB * sizeof(hf), cudaMemcpyDeviceToDevice);
    cudaMemsetAsync(HHp(1, 0), 0, HB * sizeof(hf));
    cudaMemsetAsync(HHp(2, 0), 0, HB * sizeof(hf));
    cudaMemsetAsync(c, 0, 3 * HB * sizeof(float));

    // ---- decoder ----
    cudaMemsetAsync(bar, 0, 2 * sizeof(unsigned));
    dec_persist<<<NCTA, 256, SMEM_SZ>>>(p);
}

// round 11
// speedup vs baseline: 1.5789x; 1.5789x over previous
#include <cuda_runtime.h>
#include <cuda_fp16.h>
#include <cstdint>
#include <cstddef>

typedef __half hf;

// ---------------- tile constants ----------------
#define TM    64
#define ROWB  272                 // 256B row + 16B pad -> conflict-free ldmatrix
#define OFF_A  0
#define OFF_B  17408              // 64*272
#define STAGE  34816
#define NSTG   3
#define SMEM_SZ (NSTG * STAGE)    // 104448 B
#define NCTA  128                 // LSTM CTAs
#define NHEAD 20                  // head CTAs (decoder)
#define HB    131072              // 64*2048 elems

// ---------------- asm helpers ----------------
__device__ __forceinline__ void cpa(uint32_t d, const void* s) {
    asm volatile("cp.async.cg.shared.global [%0], [%1], 16;" :: "r"(d), "l"(s));
}
__device__ __forceinline__ void cpcommit() {
    asm volatile("cp.async.commit_group;" ::: "memory");
}
template <int N> __device__ __forceinline__ void cpwait() {
    asm volatile("cp.async.wait_group %0;" :: "n"(N) : "memory");
}
#define LDSM4(R, addr) \
    asm volatile("ldmatrix.sync.aligned.m8n8.x4.shared.b16 {%0,%1,%2,%3}, [%4];" \
        : "=r"((R)[0]), "=r"((R)[1]), "=r"((R)[2]), "=r"((R)[3]) : "r"(addr))
#define MMA(D, A, b0, b1) \
    asm volatile("mma.sync.aligned.m16n8k16.row.col.f32.f16.f16.f32 " \
        "{%0,%1,%2,%3}, {%4,%5,%6,%7}, {%8,%9}, {%0,%1,%2,%3};" \
        : "+f"((D)[0]), "+f"((D)[1]), "+f"((D)[2]), "+f"((D)[3]) \
        : "r"((A)[0]), "r"((A)[1]), "r"((A)[2]), "r"((A)[3]), "r"(b0), "r"(b1))

// ---------------- scratch ----------------
#define LWF 16777216               // 8192*2048
#define WCATN 33554432             // 8192*4096
__device__ hf g_wcat[5 * WCATN];                     // enc l1,l2; dec l0,l1,l2
__device__ hf g_ewhh0[LWF];
__device__ hf g_ewih0[LWF];
__device__ hf g_fc1w[4194304], g_fc2w[2097152];
__device__ hf g_fd1w[2097152], g_fd2w[4194304];
__device__ hf g_xh[4194304];
__device__ hf g_f1a[1048576];
__device__ hf g_f2a[2097152];
__device__ hf g_d1a[65536];                          // [64,1024]
__device__ hf g_hH[6 * HB];                          // [layer][parity]
__device__ float g_pre[16 * 524288];
__device__ float g_c[3 * HB];
__device__ unsigned g_bar[8];   // [0]cnt,[1]gen (LSTM) [2]cnt,[3]gen (head) [4]step [5]headdone

// ===========================================================================
// prepass kernels
// ===========================================================================
struct SplitArgs {
    const float* s[6];
    hf* h[6];
    long off4[7];
};

__global__ void __launch_bounds__(256) split_all(SplitArgs a)
{
    const long total = a.off4[6];
    for (long v = (long)blockIdx.x * 256 + threadIdx.x; v < total;
         v += (long)gridDim.x * 256) {
        int seg = 0;
#pragma unroll
        for (int i = 0; i < 5; i++) seg += (v >= a.off4[i + 1]) ? 1 : 0;
        long e = (v - a.off4[seg]) * 4;
        float4 x = *(const float4*)(a.s[seg] + e);
        hf h0 = __float2half_rn(x.x), h1 = __float2half_rn(x.y);
        hf h2 = __float2half_rn(x.z), h3 = __float2half_rn(x.w);
        uint2 ph;
        ph.x = (uint32_t)*(uint16_t*)&h0 | ((uint32_t)*(uint16_t*)&h1 << 16);
        ph.y = (uint32_t)*(uint16_t*)&h2 | ((uint32_t)*(uint16_t*)&h3 << 16);
        *(uint2*)(a.h[seg] + e) = ph;
    }
}

__global__ void __launch_bounds__(256) lstm_pack(
    const float* __restrict__ wih, const float* __restrict__ whh,
    hf* __restrict__ dst, int hasx)
{
    const int K = hasx ? 4096 : 2048;
    const long total = (long)8192 * K / 4;
    for (long v = (long)blockIdx.x * 256 + threadIdx.x; v < total;
         v += (long)gridDim.x * 256) {
        int r = (int)(v / (K >> 2));
        int c = (int)(v % (K >> 2)) * 4;
        int gate = (r >> 4) & 3, jblk = r >> 6, jin = r & 15;
        int orig = gate * 2048 + jblk * 16 + jin;
        const float* src = (c < 2048 || !hasx)
            ? (hasx ? wih : whh) + (size_t)orig * 2048 + (c & 2047)
            : whh + (size_t)orig * 2048 + (c - 2048);
        float4 x = *(const float4*)src;
        hf h0 = __float2half_rn(x.x), h1 = __float2half_rn(x.y);
        hf h2 = __float2half_rn(x.z), h3 = __float2half_rn(x.w);
        uint2 ph;
        ph.x = (uint32_t)*(uint16_t*)&h0 | ((uint32_t)*(uint16_t*)&h1 << 16);
        ph.y = (uint32_t)*(uint16_t*)&h2 | ((uint32_t)*(uint16_t*)&h3 << 16);
        *(uint2*)(dst + (size_t)r * K + c) = ph;
    }
}

// ===========================================================================
// 1-term GEMM mainloop, K-chunks of 128, 3-stage pipeline.
// ===========================================================================
__device__ __forceinline__ void run_gemm(
    const hf* __restrict__ W, int K,
    const hf* __restrict__ Bx, int Kx, int ldbx,
    const hf* __restrict__ Bh, int ldbh,
    uint32_t sb, float acc[2][2][4])
{
    const int t = threadIdx.x;
    const int NC = K >> 7;
    const int r0 = t >> 4, seg = t & 15;
    __syncthreads();     // previous phase's smem use complete
    auto issue = [&](int chunk) {
        if (chunk < NC) {
            const uint32_t st = sb + (chunk % NSTG) * STAGE;
            const int kg = chunk << 7;
            const hf* b; int ks, ldb;
            if (kg < Kx) { b = Bx; ks = kg; ldb = ldbx; }
            else         { b = Bh; ks = kg - Kx; ldb = ldbh; }
#pragma unroll
            for (int i = 0; i < 4; i++) {
                int row = r0 + i * 16;
                uint32_t dd = st + row * ROWB + seg * 16;
                cpa(dd + OFF_A, W + (size_t)row * K   + kg + seg * 8);
                cpa(dd + OFF_B, b + (size_t)row * ldb + ks + seg * 8);
            }
        }
        cpcommit();
    };
    issue(0); issue(1);

    const int w = t >> 5, lane = t & 31;
    const int moff = (w & 1) * 32, noff = (w >> 1) * 16;
    const int arow = lane & 15, ahalf = lane >> 4;
    const int bj = lane >> 3;
    const int brow = ((bj >> 1) * 8) + (lane & 7), bkh = bj & 1;

#pragma unroll
    for (int mi = 0; mi < 2; mi++)
#pragma unroll
        for (int nj = 0; nj < 2; nj++)
#pragma unroll
            for (int q = 0; q < 4; q++) acc[mi][nj][q] = 0.f;

    for (int s = 0; s < NC; s++) {
        cpwait<1>();
        __syncthreads();
        const uint32_t st = sb + (s % NSTG) * STAGE;
#pragma unroll
        for (int k16 = 0; k16 < 8; k16++) {
            const int kb = k16 * 32;
            uint32_t ah[2][4], bb[4];
#pragma unroll
            for (int mi = 0; mi < 2; mi++) {
                uint32_t ra = (uint32_t)((moff + mi * 16 + arow) * ROWB + kb + ahalf * 16);
                LDSM4(ah[mi], st + OFF_A + ra);
            }
            uint32_t rb = (uint32_t)((noff + brow) * ROWB + kb + bkh * 16);
            LDSM4(bb, st + OFF_B + rb);
#pragma unroll
            for (int mi = 0; mi < 2; mi++)
#pragma unroll
                for (int nj = 0; nj < 2; nj++)
                    MMA(acc[mi][nj], ah[mi], bb[nj * 2], bb[nj * 2 + 1]);
        }
        issue(s + 2);
    }
}

__device__ __forceinline__ void stage_cs(float acc[2][2][4], float* cs)
{
    const int t = threadIdx.x;
    const int w = t >> 5, lane = t & 31;
    const int moff = (w & 1) * 32, noff = (w >> 1) * 16;
    const int rr = lane >> 2, cc = (lane & 3) * 2;
    __syncthreads();
#pragma unroll
    for (int mi = 0; mi < 2; mi++)
#pragma unroll
        for (int nj = 0; nj < 2; nj++) {
            int m = moff + mi * 16 + rr;
            int n = noff + nj * 8 + cc;
            cs[n * 68 + m]           = acc[mi][nj][0];
            cs[(n + 1) * 68 + m]     = acc[mi][nj][1];
            cs[n * 68 + m + 8]       = acc[mi][nj][2];
            cs[(n + 1) * 68 + m + 8] = acc[mi][nj][3];
        }
    __syncthreads();
}

__device__ __forceinline__ void barx(unsigned* cnt, unsigned* gen,
                                     unsigned& mygen, unsigned total)
{
    __threadfence();
    __syncthreads();
    if (threadIdx.x == 0) {
        mygen += 1;
        unsigned prev = atomicAdd(cnt, 1u);
        if (prev == total - 1) {
            atomicExch(cnt, 0u);
            __threadfence();
            atomicExch(gen, mygen);
        } else {
            while (atomicAdd(gen, 0u) < mygen) __nanosleep(64);
            __threadfence();
        }
    }
    __syncthreads();
}

// ===========================================================================
// batched FC GEMM (prepass-stage)
// ===========================================================================
__global__ void __launch_bounds__(256)
gemm_ms(const hf* __restrict__ A0, const hf* __restrict__ B0,
        const float* __restrict__ bias,
        float* __restrict__ outf, hf* __restrict__ outh,
        int K, int ldc, int dual)
{
    extern __shared__ char smem[];
    const uint32_t sb = (uint32_t)__cvta_generic_to_shared(smem);
    const int t = threadIdx.x;
    const int fbase = blockIdx.x * TM;
    const int nbase = blockIdx.y * 64;

    float acc[2][2][4];
    run_gemm(A0 + (size_t)fbase * K, K,
             B0 + (size_t)nbase * K, K, K, nullptr, 0, sb, acc);

    const int w = t >> 5, lane = t & 31;
    const int moff = (w & 1) * 32, noff = (w >> 1) * 16;
    const int rr = lane >> 2, cc = (lane & 3) * 2;

    if (dual == 2) {
        float* po = outf + (size_t)blockIdx.y * 524288;
#pragma unroll
        for (int mi = 0; mi < 2; mi++)
#pragma unroll
            for (int nj = 0; nj < 2; nj++) {
                int m = moff + mi * 16 + rr;
                int n = noff + nj * 8 + cc;
                *(float2*)(po + (size_t)(fbase + m) * 64 + n) =
                    make_float2(acc[mi][nj][0], acc[mi][nj][1]);
                *(float2*)(po + (size_t)(fbase + m + 8) * 64 + n) =
                    make_float2(acc[mi][nj][2], acc[mi][nj][3]);
            }
        return;
    }

    float* cs = (float*)smem;
    stage_cs(acc, cs);
    const int b = t >> 2, j0 = (t & 3) * 16;
    const float* bp = bias + fbase + j0;
    hf* dh = outh + (size_t)(nbase + b) * ldc + fbase + j0;
#pragma unroll
    for (int j = 0; j < 16; j++) {
        float v = fmaxf(cs[b * 68 + j0 + j] + bp[j], 0.f);
        dh[j] = __float2half_rn(v);
    }
}

// ===========================================================================
// persistent kernels
// ===========================================================================
struct PP {
    const hf *wcat, *ewhh0;
    const float *pre, *en_b, *de_b;
    hf *hH;
    float *c;
    const hf *fd1w, *fd2w;
    const float *fd1b, *fd2b;
    hf *d1a;
    float *out;
    unsigned *bar;
};

__device__ __forceinline__ void lstm_cell_epi(
    float acc[2][2][4], float* cs, const float* pre, const float* bias,
    float* c, hf* hh, int jg0)
{
    stage_cs(acc, cs);
    const int t = threadIdx.x;
    const int b = t >> 2, j4 = (t & 3) * 4;
    float4 cold = *(const float4*)(c + (size_t)b * 2048 + jg0 + j4);
    float cn[4]; hf hi4[4];
#pragma unroll
    for (int q = 0; q < 4; q++) {
        const int j = j4 + q, jg = jg0 + j;
        float iv = cs[b * 68 + j];
        float fv = cs[b * 68 + 16 + j];
        float gv = cs[b * 68 + 32 + j];
        float ov = cs[b * 68 + 48 + j];
        if (pre) {
            iv += pre[(size_t)(jg) * 64 + b];
            fv += pre[(size_t)(2048 + jg) * 64 + b];
            gv += pre[(size_t)(4096 + jg) * 64 + b];
            ov += pre[(size_t)(6144 + jg) * 64 + b];
        }
        iv += bias[jg]; fv += bias[2048 + jg];
        gv += bias[4096 + jg]; ov += bias[6144 + jg];
        float si = 1.f / (1.f + __expf(-iv));
        float sf = 1.f / (1.f + __expf(-fv));
        float so = 1.f / (1.f + __expf(-ov));
        float c2 = sf * (&cold.x)[q] + si * tanhf(gv);
        float h2 = so * tanhf(c2);
        cn[q] = c2;
        hi4[q] = __float2half_rn(h2);
    }
    *(float4*)(c + (size_t)b * 2048 + jg0 + j4) = *(float4*)cn;
    *(uint2*)(hh + (size_t)b * 2048 + jg0 + j4) = *(uint2*)hi4;
}

__global__ void __launch_bounds__(256)
enc_persist(PP p)
{
    extern __shared__ char smem[];
    const uint32_t sb = (uint32_t)__cvta_generic_to_shared(smem);
    float* cs = (float*)smem;
    const int bid = blockIdx.x;
    const int fbase = bid * TM, jg0 = bid * 16;
    unsigned mygen = 0;
    float acc[2][2][4];
    auto HHp = [&](int l, int pr) { return p.hH + (size_t)(l * 2 + pr) * HB; };

    for (int t16 = 0; t16 < 16; t16++) {
        const int rp = t16 & 1, wp = 1 - rp;
        run_gemm(p.ewhh0 + (size_t)fbase * 2048, 2048,
                 nullptr, 0, 0, HHp(0, rp), 2048, sb, acc);
        lstm_cell_epi(acc, cs, p.pre + (size_t)t16 * 524288, p.en_b,
                      p.c, HHp(0, wp), jg0);
        barx(p.bar, p.bar + 1, mygen, NCTA);
        run_gemm(p.wcat + (size_t)0 * WCATN + (size_t)fbase * 4096, 4096,
                 HHp(0, wp), 2048, 2048, HHp(1, rp), 2048, sb, acc);
        lstm_cell_epi(acc, cs, nullptr, p.en_b + 8192,
                      p.c + HB, HHp(1, wp), jg0);
        barx(p.bar, p.bar + 1, mygen, NCTA);
        run_gemm(p.wcat + (size_t)1 * WCATN + (size_t)fbase * 4096, 4096,
                 HHp(1, wp), 2048, 2048, HHp(2, rp), 2048, sb, acc);
        lstm_cell_epi(acc, cs, nullptr, p.en_b + 16384,
                      p.c + 2 * HB, HHp(2, wp), jg0);
        barx(p.bar, p.bar + 1, mygen, NCTA);
    }
}

__global__ void __launch_bounds__(256)
dec_persist(PP p)
{
    extern __shared__ char smem[];
    const uint32_t sb = (uint32_t)__cvta_generic_to_shared(smem);
    float* cs = (float*)smem;
    const int bid = blockIdx.x;
    unsigned mygen = 0;
    float acc[2][2][4];
    auto HHp = [&](int l, int pr) { return p.hH + (size_t)(l * 2 + pr) * HB; };

    if (bid < NCTA) {
        // ---------------- LSTM CTAs ----------------
        const int fbase = bid * TM, jg0 = bid * 16;
        for (int t16 = 0; t16 < 16; t16++) {
            const int rp = t16 & 1, wp = 1 - rp;
            run_gemm(p.wcat + (size_t)2 * WCATN + (size_t)fbase * 4096, 4096,
                     HHp(2, rp), 2048, 2048, HHp(0, rp), 2048, sb, acc);
            lstm_cell_epi(acc, cs, nullptr, p.de_b, p.c, HHp(0, wp), jg0);
            barx(p.bar, p.bar + 1, mygen, NCTA);
            run_gemm(p.wcat + (size_t)3 * WCATN + (size_t)fbase * 4096, 4096,
                     HHp(0, wp), 2048, 2048, HHp(1, rp), 2048, sb, acc);
            lstm_cell_epi(acc, cs, nullptr, p.de_b + 8192,
                          p.c + HB, HHp(1, wp), jg0);
            barx(p.bar, p.bar + 1, mygen, NCTA);
            // before overwriting h2 (parity wp, same as step t16-2), ensure
            // head consumed h2(t16-2): headdone >= t16-1
            if (t16 >= 2) {
                if (threadIdx.x == 0)
                    while (atomicAdd(p.bar + 5, 0u) < (unsigned)(t16 - 1))
                        __nanosleep(64);
                __syncthreads();
            }
            run_gemm(p.wcat + (size_t)4 * WCATN + (size_t)fbase * 4096, 4096,
                     HHp(1, wp), 2048, 2048, HHp(2, rp), 2048, sb, acc);
            lstm_cell_epi(acc, cs, nullptr, p.de_b + 16384,
                          p.c + 2 * HB, HHp(2, wp), jg0);
            barx(p.bar, p.bar + 1, mygen, NCTA);
            if (bid == 0 && threadIdx.x == 0)
                atomicExch(p.bar + 4, (unsigned)(t16 + 1));   // h2(t16) ready
        }
    } else {
        // ---------------- head CTAs ----------------
        const int hbid = bid - NCTA;   // 0..NHEAD-1
        unsigned hgen = 0;
        for (int t16 = 0; t16 < 16; t16++) {
            if (threadIdx.x == 0)
                while (atomicAdd(p.bar + 4, 0u) < (unsigned)(t16 + 1))
                    __nanosleep(128);
            __threadfence();
            __syncthreads();
            const int wp = 1 - (t16 & 1);
            // fd1: CTAs 0..15, one 64-row tile each, K=2048 from h2(wp)
            if (hbid < 16) {
                const int fbase = hbid * TM;
                run_gemm(p.fd1w + (size_t)fbase * 2048, 2048,
                         HHp(2, wp), 2048, 2048, nullptr, 0, sb, acc);
                stage_cs(acc, cs);
                const int t = threadIdx.x;
                const int b = t >> 2, j0 = (t & 3) * 16;
                const float* bp = p.fd1b + fbase + j0;
                hf* dh = p.d1a + (size_t)b * 1024 + fbase + j0;
#pragma unroll
                for (int j = 0; j < 16; j++) {
                    float v = fmaxf(cs[b * 68 + j0 + j] + bp[j], 0.f);
                    dh[j] = __float2half_rn(v);
                }
            }
            barx(p.bar + 2, p.bar + 3, hgen, NHEAD);
            if (hbid == 0 && threadIdx.x == 0)
                atomicExch(p.bar + 5, (unsigned)(t16 + 1));   // h2(t16) consumed
            // fd2: 64 tiles over NHEAD CTAs
            for (int idx = hbid; idx < 64; idx += NHEAD) {
                const int f2 = idx * TM;
                run_gemm(p.fd2w + (size_t)f2 * 1024, 1024,
                         p.d1a, 1024, 1024, nullptr, 0, sb, acc);
                stage_cs(acc, cs);
                const int t = threadIdx.x;
                const int b = t >> 2, j0 = (t & 3) * 16;
                const float* bp = p.fd2b + f2 + j0;
                float* dst = p.out + (size_t)t16 * 262144 + (size_t)b * 4096 + f2 + j0;
#pragma unroll
                for (int j = 0; j < 16; j++) {
                    float v = cs[b * 68 + j0 + j] + bp[j];
                    dst[j] = 1.f / (1.f + __expf(-v));
                }
            }
            barx(p.bar + 2, p.bar + 3, hgen, NHEAD);   // d1a free before next fd1
        }
    }
}

extern "C" void kernel_launch(void* const* d_in, const int* in_sizes, int n_in,
                              void* d_out, int out_size)
{
    const float* x        = (const float*)d_in[0];
    const float* fc_en1_w = (const float*)d_in[1];
    const float* fc_en1_b = (const float*)d_in[2];
    const float* fc_en2_w = (const float*)d_in[3];
    const float* fc_en2_b = (const float*)d_in[4];
    const float* en_wih   = (const float*)d_in[5];
    const float* en_whh   = (const float*)d_in[6];
    const float* en_b     = (const float*)d_in[7];
    const float* de_wih   = (const float*)d_in[8];
    const float* de_whh   = (const float*)d_in[9];
    const float* de_b     = (const float*)d_in[10];
    const float* fc_de1_w = (const float*)d_in[11];
    const float* fc_de1_b = (const float*)d_in[12];
    const float* fc_de2_w = (const float*)d_in[13];
    const float* fc_de2_b = (const float*)d_in[14];
    float* out = (float*)d_out;

    hf *wcat, *ewhh0, *ewih0, *fc1w, *fc2w, *fd1w, *fd2w;
    hf *xh, *f1a, *f2a, *d1a, *hH;
    float *pre, *c;
    unsigned* bar;
    cudaGetSymbolAddress((void**)&wcat, g_wcat);
    cudaGetSymbolAddress((void**)&ewhh0, g_ewhh0);
    cudaGetSymbolAddress((void**)&ewih0, g_ewih0);
    cudaGetSymbolAddress((void**)&fc1w, g_fc1w);  cudaGetSymbolAddress((void**)&fc2w, g_fc2w);
    cudaGetSymbolAddress((void**)&fd1w, g_fd1w);  cudaGetSymbolAddress((void**)&fd2w, g_fd2w);
    cudaGetSymbolAddress((void**)&xh, g_xh);
    cudaGetSymbolAddress((void**)&f1a, g_f1a);    cudaGetSymbolAddress((void**)&f2a, g_f2a);
    cudaGetSymbolAddress((void**)&d1a, g_d1a);    cudaGetSymbolAddress((void**)&hH, g_hH);
    cudaGetSymbolAddress((void**)&pre, g_pre);    cudaGetSymbolAddress((void**)&c, g_c);
    cudaGetSymbolAddress((void**)&bar, g_bar);

    cudaFuncSetAttribute(gemm_ms,     cudaFuncAttributeMaxDynamicSharedMemorySize, SMEM_SZ);
    cudaFuncSetAttribute(enc_persist, cudaFuncAttributeMaxDynamicSharedMemorySize, SMEM_SZ);
    cudaFuncSetAttribute(dec_persist, cudaFuncAttributeMaxDynamicSharedMemorySize, SMEM_SZ);

    auto HHp = [&](int l, int pr) { return hH + (size_t)(l * 2 + pr) * HB; };

    // ---- prepass ----
    {
        SplitArgs a;
        const float* srcs[6] = {en_wih, fc_en1_w, fc_en2_w, fc_de1_w, fc_de2_w, x};
        hf* hs[6] = {ewih0, fc1w, fc2w, fd1w, fd2w, xh};
        long ns[6] = {LWF, 4194304, 2097152, 2097152, 4194304, 4194304};
        long acc = 0;
        for (int i = 0; i < 6; i++) {
            a.s[i] = srcs[i]; a.h[i] = hs[i];
            a.off4[i] = acc; acc += ns[i] / 4;
        }
        a.off4[6] = acc;
        split_all<<<1024, 256>>>(a);
    }
    lstm_pack<<<2048, 256>>>(en_wih + (size_t)1 * LWF, en_whh + (size_t)1 * LWF,
                             wcat + (size_t)0 * WCATN, 1);
    lstm_pack<<<2048, 256>>>(en_wih + (size_t)2 * LWF, en_whh + (size_t)2 * LWF,
                             wcat + (size_t)1 * WCATN, 1);
    lstm_pack<<<2048, 256>>>(de_wih,                   de_whh,
                             wcat + (size_t)2 * WCATN, 1);
    lstm_pack<<<2048, 256>>>(de_wih + (size_t)1 * LWF, de_whh + (size_t)1 * LWF,
                             wcat + (size_t)3 * WCATN, 1);
    lstm_pack<<<2048, 256>>>(de_wih + (size_t)2 * LWF, de_whh + (size_t)2 * LWF,
                             wcat + (size_t)4 * WCATN, 1);
    lstm_pack<<<1024, 256>>>(nullptr, en_whh, ewhh0, 0);

    cudaMemsetAsync(hH, 0, 6 * HB * sizeof(hf));
    cudaMemsetAsync(c,  0, 3 * HB * sizeof(float));

    // ---- batched encoder FCs + l0 pre-gates ----
    gemm_ms<<<dim3(16, 16), 256, SMEM_SZ>>>(fc1w, xh, fc_en1_b,
        nullptr, f1a, 4096, 1024, 0);
    gemm_ms<<<dim3(32, 16), 256, SMEM_SZ>>>(fc2w, f1a, fc_en2_b,
        nullptr, f2a, 1024, 2048, 0);
    gemm_ms<<<dim3(128, 16), 256, SMEM_SZ>>>(ewih0, f2a, nullptr,
        pre, nullptr, 2048, 0, 2);

    PP p;
    p.wcat = wcat; p.ewhh0 = ewhh0; p.pre = pre;
    p.en_b = en_b; p.de_b = de_b;
    p.hH = hH; p.c = c;
    p.fd1w = fd1w; p.fd2w = fd2w; p.fd1b = fc_de1_b; p.fd2b = fc_de2_b;
    p.d1a = d1a; p.out = out; p.bar = bar;

    // ---- encoder ----
    cudaMemsetAsync(bar, 0, 8 * sizeof(unsigned));
    enc_persist<<<NCTA, 256, SMEM_SZ>>>(p);

    // ---- decoder init: h0(p0) = enc h2(p0); h1,h2(p0) zero; c zero ----
    cudaMemcpyAsync(HHp(0, 0), HHp(2, 0), HB * sizeof(hf), cudaMemcpyDeviceToDevice);
    cudaMemsetAsync(HHp(1, 0), 0, HB * sizeof(hf));
    cudaMemsetAsync(HHp(2, 0), 0, HB * sizeof(hf));
    cudaMemsetAsync(c, 0, 3 * HB * sizeof(float));

    // ---- decoder (LSTM CTAs + concurrent head CTAs, one launch) ----
    cudaMemsetAsync(bar, 0, 8 * sizeof(unsigned));
    dec_persist<<<NCTA + NHEAD, 256, SMEM_SZ>>>(p);
}

// round 13
// speedup vs baseline: 1.6761x; 1.0616x over previous
#include <cuda_runtime.h>
#include <cuda_fp16.h>
#include <cstdint>
#include <cstddef>

typedef __half hf;

// ---------------- tile constants ----------------
#define TM    64
#define ROWB  272                 // 256B row + 16B pad -> conflict-free ldmatrix
#define OFF_A  0
#define OFF_B  17408              // 64*272
#define STAGE  34816
#define NSTG   4
#define SMEM_SZ (NSTG * STAGE)    // 139264 B -> 1 CTA/SM
#define CS_OFF (3 * STAGE + OFF_B)  // epilogue staging (stage3 B half, 17408 B)
#define NCTA  128                 // LSTM CTAs
#define NHEAD 20                  // head CTAs (decoder)
#define HB    131072              // 64*2048 elems

// ---------------- asm helpers ----------------
__device__ __forceinline__ void cpa(uint32_t d, const void* s) {
    asm volatile("cp.async.cg.shared.global [%0], [%1], 16;" :: "r"(d), "l"(s));
}
__device__ __forceinline__ void cpcommit() {
    asm volatile("cp.async.commit_group;" ::: "memory");
}
template <int N> __device__ __forceinline__ void cpwait() {
    asm volatile("cp.async.wait_group %0;" :: "n"(N) : "memory");
}
#define LDSM4(R, addr) \
    asm volatile("ldmatrix.sync.aligned.m8n8.x4.shared.b16 {%0,%1,%2,%3}, [%4];" \
        : "=r"((R)[0]), "=r"((R)[1]), "=r"((R)[2]), "=r"((R)[3]) : "r"(addr))
#define MMA(D, A, b0, b1) \
    asm volatile("mma.sync.aligned.m16n8k16.row.col.f32.f16.f16.f32 " \
        "{%0,%1,%2,%3}, {%4,%5,%6,%7}, {%8,%9}, {%0,%1,%2,%3};" \
        : "+f"((D)[0]), "+f"((D)[1]), "+f"((D)[2]), "+f"((D)[3]) \
        : "r"((A)[0]), "r"((A)[1]), "r"((A)[2]), "r"((A)[3]), "r"(b0), "r"(b1))

// ---------------- scratch ----------------
#define LWF 16777216               // 8192*2048
#define WCATN 33554432             // 8192*4096
__device__ hf g_wcat[5 * WCATN];                     // enc l1,l2; dec l0,l1,l2
__device__ hf g_ewhh0[LWF];
__device__ hf g_ewih0[LWF];
__device__ hf g_fc1w[4194304], g_fc2w[2097152];
__device__ hf g_fd1w[2097152], g_fd2w[4194304];
__device__ hf g_xh[4194304];
__device__ hf g_f1a[1048576];
__device__ hf g_f2a[2097152];
__device__ hf g_d1a[65536];                          // [64,1024]
__device__ hf g_hH[6 * HB];                          // [layer][parity]
__device__ float g_pre[16 * 524288];
__device__ float g_c[3 * HB];
__device__ unsigned g_bar[8];   // [0]cnt,[1]gen (LSTM) [2]cnt,[3]gen (head) [4]step [5]headdone

// ===========================================================================
// prepass kernels
// ===========================================================================
struct SplitArgs {
    const float* s[6];
    hf* h[6];
    long off4[7];
};

__global__ void __launch_bounds__(256) split_all(SplitArgs a)
{
    const long total = a.off4[6];
    for (long v = (long)blockIdx.x * 256 + threadIdx.x; v < total;
         v += (long)gridDim.x * 256) {
        int seg = 0;
#pragma unroll
        for (int i = 0; i < 5; i++) seg += (v >= a.off4[i + 1]) ? 1 : 0;
        long e = (v - a.off4[seg]) * 4;
        float4 x = *(const float4*)(a.s[seg] + e);
        hf h0 = __float2half_rn(x.x), h1 = __float2half_rn(x.y);
        hf h2 = __float2half_rn(x.z), h3 = __float2half_rn(x.w);
        uint2 ph;
        ph.x = (uint32_t)*(uint16_t*)&h0 | ((uint32_t)*(uint16_t*)&h1 << 16);
        ph.y = (uint32_t)*(uint16_t*)&h2 | ((uint32_t)*(uint16_t*)&h3 << 16);
        *(uint2*)(a.h[seg] + e) = ph;
    }
}

__global__ void __launch_bounds__(256) lstm_pack(
    const float* __restrict__ wih, const float* __restrict__ whh,
    hf* __restrict__ dst, int hasx)
{
    const int K = hasx ? 4096 : 2048;
    const long total = (long)8192 * K / 4;
    for (long v = (long)blockIdx.x * 256 + threadIdx.x; v < total;
         v += (long)gridDim.x * 256) {
        int r = (int)(v / (K >> 2));
        int c = (int)(v % (K >> 2)) * 4;
        int gate = (r >> 4) & 3, jblk = r >> 6, jin = r & 15;
        int orig = gate * 2048 + jblk * 16 + jin;
        const float* src = (c < 2048 || !hasx)
            ? (hasx ? wih : whh) + (size_t)orig * 2048 + (c & 2047)
            : whh + (size_t)orig * 2048 + (c - 2048);
        float4 x = *(const float4*)src;
        hf h0 = __float2half_rn(x.x), h1 = __float2half_rn(x.y);
        hf h2 = __float2half_rn(x.z), h3 = __float2half_rn(x.w);
        uint2 ph;
        ph.x = (uint32_t)*(uint16_t*)&h0 | ((uint32_t)*(uint16_t*)&h1 << 16);
        ph.y = (uint32_t)*(uint16_t*)&h2 | ((uint32_t)*(uint16_t*)&h3 << 16);
        *(uint2*)(dst + (size_t)r * K + c) = ph;
    }
}

// ===========================================================================
// A-prefetch: issue weight-only cp.asyncs for next phase's chunks 0,1
// (stages 0,1 A-regions; 2 commit groups). Safe: all warps have finished
// reading stages 0,1 (iteration-top syncs through chunk NC-2).
// ===========================================================================
__device__ __forceinline__ void gemm_prefA(const hf* __restrict__ W, int K,
                                           uint32_t sb)
{
    const int t = threadIdx.x;
    const int r0 = t >> 4, seg = t & 15;
#pragma unroll
    for (int chunk = 0; chunk < 2; chunk++) {
        const uint32_t st = sb + chunk * STAGE;
#pragma unroll
        for (int i = 0; i < 4; i++) {
            int row = r0 + i * 16;
            cpa(st + row * ROWB + seg * 16 + OFF_A,
                W + (size_t)row * K + (chunk << 7) + seg * 8);
        }
        cpcommit();
    }
}

// ===========================================================================
// 1-term GEMM mainloop, K-chunks of 128, 4 stages.
// preA=1: A(0),A(1) already issued pre-barrier; prologue issues B0,B1,AB2.
// preA=0: prologue issues AB0,AB1,AB2. Uniform loop: cpwait<2>.
// ===========================================================================
__device__ __forceinline__ void run_gemm(
    const hf* __restrict__ W, int K,
    const hf* __restrict__ Bx, int Kx, int ldbx,
    const hf* __restrict__ Bh, int ldbh,
    uint32_t sb, float acc[2][2][4], int preA)
{
    const int t = threadIdx.x;
    const int NC = K >> 7;
    const int r0 = t >> 4, seg = t & 15;

    auto bsrc = [&](int kg, const hf*& b, int& ks, int& ldb) {
        if (kg < Kx) { b = Bx; ks = kg; ldb = ldbx; }
        else         { b = Bh; ks = kg - Kx; ldb = ldbh; }
    };
    auto issueAB = [&](int chunk) {
        if (chunk < NC) {
            const uint32_t st = sb + (chunk & 3) * STAGE;
            const int kg = chunk << 7;
            const hf* b; int ks, ldb;
            bsrc(kg, b, ks, ldb);
#pragma unroll
            for (int i = 0; i < 4; i++) {
                int row = r0 + i * 16;
                uint32_t dd = st + row * ROWB + seg * 16;
                cpa(dd + OFF_A, W + (size_t)row * K   + kg + seg * 8);
                cpa(dd + OFF_B, b + (size_t)row * ldb + ks + seg * 8);
            }
        }
        cpcommit();
    };
    auto issueB = [&](int chunk) {
        const uint32_t st = sb + (chunk & 3) * STAGE;
        const int kg = chunk << 7;
        const hf* b; int ks, ldb;
        bsrc(kg, b, ks, ldb);
#pragma unroll
        for (int i = 0; i < 4; i++) {
            int row = r0 + i * 16;
            cpa(st + row * ROWB + seg * 16 + OFF_B,
                b + (size_t)row * ldb + ks + seg * 8);
        }
        cpcommit();
    };

    if (preA) {
        issueB(0); issueB(1); issueAB(2);
    } else {
        __syncthreads();
        issueAB(0); issueAB(1); issueAB(2);
    }

    const int w = t >> 5, lane = t & 31;
    const int moff = (w & 1) * 32, noff = (w >> 1) * 16;
    const int arow = lane & 15, ahalf = lane >> 4;
    const int bj = lane >> 3;
    const int brow = ((bj >> 1) * 8) + (lane & 7), bkh = bj & 1;

#pragma unroll
    for (int mi = 0; mi < 2; mi++)
#pragma unroll
        for (int nj = 0; nj < 2; nj++)
#pragma unroll
            for (int q = 0; q < 4; q++) acc[mi][nj][q] = 0.f;

    for (int s = 0; s < NC; s++) {
        cpwait<2>();
        __syncthreads();
        const uint32_t st = sb + (s & 3) * STAGE;
#pragma unroll
        for (int k16 = 0; k16 < 8; k16++) {
            const int kb = k16 * 32;
            uint32_t ah[2][4], bb[4];
#pragma unroll
            for (int mi = 0; mi < 2; mi++) {
                uint32_t ra = (uint32_t)((moff + mi * 16 + arow) * ROWB + kb + ahalf * 16);
                LDSM4(ah[mi], st + OFF_A + ra);
            }
            uint32_t rb = (uint32_t)((noff + brow) * ROWB + kb + bkh * 16);
            LDSM4(bb, st + OFF_B + rb);
#pragma unroll
            for (int mi = 0; mi < 2; mi++)
#pragma unroll
                for (int nj = 0; nj < 2; nj++)
                    MMA(acc[mi][nj], ah[mi], bb[nj * 2], bb[nj * 2 + 1]);
        }
        issueAB(s + 3);
    }
}

__device__ __forceinline__ void stage_cs(float acc[2][2][4], float* cs)
{
    const int t = threadIdx.x;
    const int w = t >> 5, lane = t & 31;
    const int moff = (w & 1) * 32, noff = (w >> 1) * 16;
    const int rr = lane >> 2, cc = (lane & 3) * 2;
    __syncthreads();
#pragma unroll
    for (int mi = 0; mi < 2; mi++)
#pragma unroll
        for (int nj = 0; nj < 2; nj++) {
            int m = moff + mi * 16 + rr;
            int n = noff + nj * 8 + cc;
            cs[n * 68 + m]           = acc[mi][nj][0];
            cs[(n + 1) * 68 + m]     = acc[mi][nj][1];
            cs[n * 68 + m + 8]       = acc[mi][nj][2];
            cs[(n + 1) * 68 + m + 8] = acc[mi][nj][3];
        }
    __syncthreads();
}

__device__ __forceinline__ void barx(unsigned* cnt, unsigned* gen,
                                     unsigned& mygen, unsigned total)
{
    __threadfence();
    __syncthreads();
    if (threadIdx.x == 0) {
        mygen += 1;
        unsigned prev = atomicAdd(cnt, 1u);
        if (prev == total - 1) {
            atomicExch(cnt, 0u);
            __threadfence();
            atomicExch(gen, mygen);
        } else {
            while (atomicAdd(gen, 0u) < mygen) __nanosleep(64);
            __threadfence();
        }
    }
    __syncthreads();
}

// ===========================================================================
// batched FC GEMM (prepass-stage)
// ===========================================================================
__global__ void __launch_bounds__(256)
gemm_ms(const hf* __restrict__ A0, const hf* __restrict__ B0,
        const float* __restrict__ bias,
        float* __restrict__ outf, hf* __restrict__ outh,
        int K, int ldc, int dual)
{
    extern __shared__ char smem[];
    const uint32_t sb = (uint32_t)__cvta_generic_to_shared(smem);
    const int t = threadIdx.x;
    const int fbase = blockIdx.x * TM;
    const int nbase = blockIdx.y * 64;

    float acc[2][2][4];
    run_gemm(A0 + (size_t)fbase * K, K,
             B0 + (size_t)nbase * K, K, K, nullptr, 0, sb, acc, 0);

    const int w = t >> 5, lane = t & 31;
    const int moff = (w & 1) * 32, noff = (w >> 1) * 16;
    const int rr = lane >> 2, cc = (lane & 3) * 2;

    if (dual == 2) {
        float* po = outf + (size_t)blockIdx.y * 524288;
#pragma unroll
        for (int mi = 0; mi < 2; mi++)
#pragma unroll
            for (int nj = 0; nj < 2; nj++) {
                int m = moff + mi * 16 + rr;
                int n = noff + nj * 8 + cc;
                *(float2*)(po + (size_t)(fbase + m) * 64 + n) =
                    make_float2(acc[mi][nj][0], acc[mi][nj][1]);
                *(float2*)(po + (size_t)(fbase + m + 8) * 64 + n) =
                    make_float2(acc[mi][nj][2], acc[mi][nj][3]);
            }
        return;
    }

    float* cs = (float*)(smem + CS_OFF);
    stage_cs(acc, cs);
    const int b = t >> 2, j0 = (t & 3) * 16;
    const float* bp = bias + fbase + j0;
    hf* dh = outh + (size_t)(nbase + b) * ldc + fbase + j0;
#pragma unroll
    for (int j = 0; j < 16; j++) {
        float v = fmaxf(cs[b * 68 + j0 + j] + bp[j], 0.f);
        dh[j] = __float2half_rn(v);
    }
}

// ===========================================================================
// persistent kernels
// ===========================================================================
struct PP {
    const hf *wcat, *ewhh0;
    const float *pre, *en_b, *de_b;
    hf *hH;
    float *c;
    const hf *fd1w, *fd2w;
    const float *fd1b, *fd2b;
    hf *d1a;
    float *out;
    unsigned *bar;
};

__device__ __forceinline__ void lstm_cell_epi(
    float acc[2][2][4], float* cs, const float* pre, const float* bias,
    float* c, hf* hh, int jg0)
{
    stage_cs(acc, cs);
    const int t = threadIdx.x;
    const int b = t >> 2, j4 = (t & 3) * 4;
    float4 cold = *(const float4*)(c + (size_t)b * 2048 + jg0 + j4);
    float cn[4]; hf hi4[4];
#pragma unroll
    for (int q = 0; q < 4; q++) {
        const int j = j4 + q, jg = jg0 + j;
        float iv = cs[b * 68 + j];
        float fv = cs[b * 68 + 16 + j];
        float gv = cs[b * 68 + 32 + j];
        float ov = cs[b * 68 + 48 + j];
        if (pre) {
            iv += pre[(size_t)(jg) * 64 + b];
            fv += pre[(size_t)(2048 + jg) * 64 + b];
            gv += pre[(size_t)(4096 + jg) * 64 + b];
            ov += pre[(size_t)(6144 + jg) * 64 + b];
        }
        iv += bias[jg]; fv += bias[2048 + jg];
        gv += bias[4096 + jg]; ov += bias[6144 + jg];
        float si = 1.f / (1.f + __expf(-iv));
        float sf = 1.f / (1.f + __expf(-fv));
        float so = 1.f / (1.f + __expf(-ov));
        float c2 = sf * (&cold.x)[q] + si * tanhf(gv);
        float h2 = so * tanhf(c2);
        cn[q] = c2;
        hi4[q] = __float2half_rn(h2);
    }
    *(float4*)(c + (size_t)b * 2048 + jg0 + j4) = *(float4*)cn;
    *(uint2*)(hh + (size_t)b * 2048 + jg0 + j4) = *(uint2*)hi4;
}

__global__ void __launch_bounds__(256)
enc_persist(PP p)
{
    extern __shared__ char smem[];
    const uint32_t sb = (uint32_t)__cvta_generic_to_shared(smem);
    float* cs = (float*)(smem + CS_OFF);
    const int bid = blockIdx.x;
    const int fbase = bid * TM, jg0 = bid * 16;
    unsigned mygen = 0;
    float acc[2][2][4];
    auto HHp = [&](int l, int pr) { return p.hH + (size_t)(l * 2 + pr) * HB; };
    const hf* w0 = p.ewhh0 + (size_t)fbase * 2048;
    const hf* w1 = p.wcat + (size_t)0 * WCATN + (size_t)fbase * 4096;
    const hf* w2 = p.wcat + (size_t)1 * WCATN + (size_t)fbase * 4096;

    for (int t16 = 0; t16 < 16; t16++) {
        const int rp = t16 & 1, wp = 1 - rp;
        run_gemm(w0, 2048, nullptr, 0, 0, HHp(0, rp), 2048, sb, acc, t16 > 0);
        gemm_prefA(w1, 4096, sb);
        lstm_cell_epi(acc, cs, p.pre + (size_t)t16 * 524288, p.en_b,
                      p.c, HHp(0, wp), jg0);
        barx(p.bar, p.bar + 1, mygen, NCTA);

        run_gemm(w1, 4096, HHp(0, wp), 2048, 2048, HHp(1, rp), 2048, sb, acc, 1);
        gemm_prefA(w2, 4096, sb);
        lstm_cell_epi(acc, cs, nullptr, p.en_b + 8192,
                      p.c + HB, HHp(1, wp), jg0);
        barx(p.bar, p.bar + 1, mygen, NCTA);

        run_gemm(w2, 4096, HHp(1, wp), 2048, 2048, HHp(2, rp), 2048, sb, acc, 1);
        if (t16 < 15) gemm_prefA(w0, 2048, sb);
        lstm_cell_epi(acc, cs, nullptr, p.en_b + 16384,
                      p.c + 2 * HB, HHp(2, wp), jg0);
        barx(p.bar, p.bar + 1, mygen, NCTA);
    }
}

__global__ void __launch_bounds__(256)
dec_persist(PP p)
{
    extern __shared__ char smem[];
    const uint32_t sb = (uint32_t)__cvta_generic_to_shared(smem);
    float* cs = (float*)(smem + CS_OFF);
    const int bid = blockIdx.x;
    unsigned mygen = 0;
    float acc[2][2][4];
    auto HHp = [&](int l, int pr) { return p.hH + (size_t)(l * 2 + pr) * HB; };

    if (bid < NCTA) {
        const int fbase = bid * TM, jg0 = bid * 16;
        const hf* w0 = p.wcat + (size_t)2 * WCATN + (size_t)fbase * 4096;
        const hf* w1 = p.wcat + (size_t)3 * WCATN + (size_t)fbase * 4096;
        const hf* w2 = p.wcat + (size_t)4 * WCATN + (size_t)fbase * 4096;
        for (int t16 = 0; t16 < 16; t16++) {
            const int rp = t16 & 1, wp = 1 - rp;
            run_gemm(w0, 4096, HHp(2, rp), 2048, 2048, HHp(0, rp), 2048,
                     sb, acc, t16 > 0);
            gemm_prefA(w1, 4096, sb);
            lstm_cell_epi(acc, cs, nullptr, p.de_b, p.c, HHp(0, wp), jg0);
            barx(p.bar, p.bar + 1, mygen, NCTA);

            run_gemm(w1, 4096, HHp(0, wp), 2048, 2048, HHp(1, rp), 2048,
                     sb, acc, 1);
            gemm_prefA(w2, 4096, sb);
            lstm_cell_epi(acc, cs, nullptr, p.de_b + 8192,
                          p.c + HB, HHp(1, wp), jg0);
            barx(p.bar, p.bar + 1, mygen, NCTA);

            // before overwriting h2(wp) (= step t16-2's buffer), ensure head
            // consumed h2(t16-2): headdone >= t16-1
            if (t16 >= 2) {
                if (threadIdx.x == 0)
                    while (atomicAdd(p.bar + 5, 0u) < (unsigned)(t16 - 1))
                        __nanosleep(64);
                __syncthreads();
            }
            run_gemm(w2, 4096, HHp(1, wp), 2048, 2048, HHp(2, rp), 2048,
                     sb, acc, 1);
            if (t16 < 15) gemm_prefA(w0, 4096, sb);
            lstm_cell_epi(acc, cs, nullptr, p.de_b + 16384,
                          p.c + 2 * HB, HHp(2, wp), jg0);
            barx(p.bar, p.bar + 1, mygen, NCTA);
            if (bid == 0 && threadIdx.x == 0)
                atomicExch(p.bar + 4, (unsigned)(t16 + 1));   // h2(t16) ready
        }
    } else {
        const int hbid = bid - NCTA;   // 0..NHEAD-1
        unsigned hgen = 0;
        for (int t16 = 0; t16 < 16; t16++) {
            if (threadIdx.x == 0)
                while (atomicAdd(p.bar + 4, 0u) < (unsigned)(t16 + 1))
                    __nanosleep(128);
            __threadfence();
            __syncthreads();
            const int wp = 1 - (t16 & 1);
            if (hbid < 16) {
                const int fbase = hbid * TM;
                run_gemm(p.fd1w + (size_t)fbase * 2048, 2048,
                         HHp(2, wp), 2048, 2048, nullptr, 0, sb, acc, 0);
                stage_cs(acc, cs);
                const int t = threadIdx.x;
                const int b = t >> 2, j0 = (t & 3) * 16;
                const float* bp = p.fd1b + fbase + j0;
                hf* dh = p.d1a + (size_t)b * 1024 + fbase + j0;
#pragma unroll
                for (int j = 0; j < 16; j++) {
                    float v = fmaxf(cs[b * 68 + j0 + j] + bp[j], 0.f);
                    dh[j] = __float2half_rn(v);
                }
            }
            barx(p.bar + 2, p.bar + 3, hgen, NHEAD);
            if (hbid == 0 && threadIdx.x == 0)
                atomicExch(p.bar + 5, (unsigned)(t16 + 1));   // h2(t16) consumed
            for (int idx = hbid; idx < 64; idx += NHEAD) {
                const int f2 = idx * TM;
                run_gemm(p.fd2w + (size_t)f2 * 1024, 1024,
                         p.d1a, 1024, 1024, nullptr, 0, sb, acc, 0);
                stage_cs(acc, cs);
                const int t = threadIdx.x;
                const int b = t >> 2, j0 = (t & 3) * 16;
                const float* bp = p.fd2b + f2 + j0;
                float* dst = p.out + (size_t)t16 * 262144 + (size_t)b * 4096 + f2 + j0;
#pragma unroll
                for (int j = 0; j < 16; j++) {
                    float v = cs[b * 68 + j0 + j] + bp[j];
                    dst[j] = 1.f / (1.f + __expf(-v));
                }
            }
            barx(p.bar + 2, p.bar + 3, hgen, NHEAD);   // d1a free before next fd1
        }
    }
}

extern "C" void kernel_launch(void* const* d_in, const int* in_sizes, int n_in,
                              void* d_out, int out_size)
{
    const float* x        = (const float*)d_in[0];
    const float* fc_en1_w = (const float*)d_in[1];
    const float* fc_en1_b = (const float*)d_in[2];
    const float* fc_en2_w = (const float*)d_in[3];
    const float* fc_en2_b = (const float*)d_in[4];
    const float* en_wih   = (const float*)d_in[5];
    const float* en_whh   = (const float*)d_in[6];
    const float* en_b     = (const float*)d_in[7];
    const float* de_wih   = (const float*)d_in[8];
    const float* de_whh   = (const float*)d_in[9];
    const float* de_b     = (const float*)d_in[10];
    const float* fc_de1_w = (const float*)d_in[11];
    const float* fc_de1_b = (const float*)d_in[12];
    const float* fc_de2_w = (const float*)d_in[13];
    const float* fc_de2_b = (const float*)d_in[14];
    float* out = (float*)d_out;

    hf *wcat, *ewhh0, *ewih0, *fc1w, *fc2w, *fd1w, *fd2w;
    hf *xh, *f1a, *f2a, *d1a, *hH;
    float *pre, *c;
    unsigned* bar;
    cudaGetSymbolAddress((void**)&wcat, g_wcat);
    cudaGetSymbolAddress((void**)&ewhh0, g_ewhh0);
    cudaGetSymbolAddress((void**)&ewih0, g_ewih0);
    cudaGetSymbolAddress((void**)&fc1w, g_fc1w);  cudaGetSymbolAddress((void**)&fc2w, g_fc2w);
    cudaGetSymbolAddress((void**)&fd1w, g_fd1w);  cudaGetSymbolAddress((void**)&fd2w, g_fd2w);
    cudaGetSymbolAddress((void**)&xh, g_xh);
    cudaGetSymbolAddress((void**)&f1a, g_f1a);    cudaGetSymbolAddress((void**)&f2a, g_f2a);
    cudaGetSymbolAddress((void**)&d1a, g_d1a);    cudaGetSymbolAddress((void**)&hH, g_hH);
    cudaGetSymbolAddress((void**)&pre, g_pre);    cudaGetSymbolAddress((void**)&c, g_c);
    cudaGetSymbolAddress((void**)&bar, g_bar);

    cudaFuncSetAttribute(gemm_ms,     cudaFuncAttributeMaxDynamicSharedMemorySize, SMEM_SZ);
    cudaFuncSetAttribute(enc_persist, cudaFuncAttributeMaxDynamicSharedMemorySize, SMEM_SZ);
    cudaFuncSetAttribute(dec_persist, cudaFuncAttributeMaxDynamicSharedMemorySize, SMEM_SZ);

    auto HHp = [&](int l, int pr) { return hH + (size_t)(l * 2 + pr) * HB; };

    // ---- prepass ----
    {
        SplitArgs a;
        const float* srcs[6] = {en_wih, fc_en1_w, fc_en2_w, fc_de1_w, fc_de2_w, x};
        hf* hs[6] = {ewih0, fc1w, fc2w, fd1w, fd2w, xh};
        long ns[6] = {LWF, 4194304, 2097152, 2097152, 4194304, 4194304};
        long acc = 0;
        for (int i = 0; i < 6; i++) {
            a.s[i] = srcs[i]; a.h[i] = hs[i];
            a.off4[i] = acc; acc += ns[i] / 4;
        }
        a.off4[6] = acc;
        split_all<<<1024, 256>>>(a);
    }
    lstm_pack<<<2048, 256>>>(en_wih + (size_t)1 * LWF, en_whh + (size_t)1 * LWF,
                             wcat + (size_t)0 * WCATN, 1);
    lstm_pack<<<2048, 256>>>(en_wih + (size_t)2 * LWF, en_whh + (size_t)2 * LWF,
                             wcat + (size_t)1 * WCATN, 1);
    lstm_pack<<<2048, 256>>>(de_wih,                   de_whh,
                             wcat + (size_t)2 * WCATN, 1);
    lstm_pack<<<2048, 256>>>(de_wih + (size_t)1 * LWF, de_whh + (size_t)1 * LWF,
                             wcat + (size_t)3 * WCATN, 1);
    lstm_pack<<<2048, 256>>>(de_wih + (size_t)2 * LWF, de_whh + (size_t)2 * LWF,
                             wcat + (size_t)4 * WCATN, 1);
    lstm_pack<<<1024, 256>>>(nullptr, en_whh, ewhh0, 0);

    cudaMemsetAsync(hH, 0, 6 * HB * sizeof(hf));
    cudaMemsetAsync(c,  0, 3 * HB * sizeof(float));

    // ---- batched encoder FCs + l0 pre-gates ----
    gemm_ms<<<dim3(16, 16), 256, SMEM_SZ>>>(fc1w, xh, fc_en1_b,
        nullptr, f1a, 4096, 1024, 0);
    gemm_ms<<<dim3(32, 16), 256, SMEM_SZ>>>(fc2w, f1a, fc_en2_b,
        nullptr, f2a, 1024, 2048, 0);
    gemm_ms<<<dim3(128, 16), 256, SMEM_SZ>>>(ewih0, f2a, nullptr,
        pre, nullptr, 2048, 0, 2);

    PP p;
    p.wcat = wcat; p.ewhh0 = ewhh0; p.pre = pre;
    p.en_b = en_b; p.de_b = de_b;
    p.hH = hH; p.c = c;
    p.fd1w = fd1w; p.fd2w = fd2w; p.fd1b = fc_de1_b; p.fd2b = fc_de2_b;
    p.d1a = d1a; p.out = out; p.bar = bar;

    // ---- encoder ----
    cudaMemsetAsync(bar, 0, 8 * sizeof(unsigned));
    enc_persist<<<NCTA, 256, SMEM_SZ>>>(p);

    // ---- decoder init: h0(p0) = enc h2(p0); h1,h2(p0) zero; c zero ----
    cudaMemcpyAsync(HHp(0, 0), HHp(2, 0), HB * sizeof(hf), cudaMemcpyDeviceToDevice);
    cudaMemsetAsync(HHp(1, 0), 0, HB * sizeof(hf));
    cudaMemsetAsync(HHp(2, 0), 0, HB * sizeof(hf));
    cudaMemsetAsync(c, 0, 3 * HB * sizeof(float));

    // ---- decoder (LSTM CTAs + concurrent head CTAs, one launch) ----
    cudaMemsetAsync(bar, 0, 8 * sizeof(unsigned));
    dec_persist<<<NCTA + NHEAD, 256, SMEM_SZ>>>(p);
}

// round 14
// speedup vs baseline: 1.7310x; 1.0328x over previous
#include <cuda_runtime.h>
#include <cuda_fp16.h>
#include <cstdint>
#include <cstddef>

typedef __half hf;

// ---------------- tile constants ----------------
#define TM    64
#define ROWB  272                 // 256B row + 16B pad -> conflict-free ldmatrix
#define OFF_A  0
#define OFF_B  17408              // 64*272
#define STAGE  34816
#define NSTG   4
#define SMEM_SZ (NSTG * STAGE)    // 139264 B -> 1 CTA/SM
#define CS_OFF (3 * STAGE + OFF_B)  // epilogue staging (stage3 B half)
#define NCTA  128                 // LSTM CTAs
#define NHEAD 20                  // head CTAs (decoder)
#define HB    131072              // 64*2048 elems

// ---------------- asm helpers ----------------
__device__ __forceinline__ void cpa(uint32_t d, const void* s) {
    asm volatile("cp.async.cg.shared.global [%0], [%1], 16;" :: "r"(d), "l"(s));
}
__device__ __forceinline__ void cpcommit() {
    asm volatile("cp.async.commit_group;" ::: "memory");
}
template <int N> __device__ __forceinline__ void cpwait() {
    asm volatile("cp.async.wait_group %0;" :: "n"(N) : "memory");
}
#define LDSM4(R, addr) \
    asm volatile("ldmatrix.sync.aligned.m8n8.x4.shared.b16 {%0,%1,%2,%3}, [%4];" \
        : "=r"((R)[0]), "=r"((R)[1]), "=r"((R)[2]), "=r"((R)[3]) : "r"(addr))
#define MMA(D, A, b0, b1) \
    asm volatile("mma.sync.aligned.m16n8k16.row.col.f32.f16.f16.f32 " \
        "{%0,%1,%2,%3}, {%4,%5,%6,%7}, {%8,%9}, {%0,%1,%2,%3};" \
        : "+f"((D)[0]), "+f"((D)[1]), "+f"((D)[2]), "+f"((D)[3]) \
        : "r"((A)[0]), "r"((A)[1]), "r"((A)[2]), "r"((A)[3]), "r"(b0), "r"(b1))

// ---------------- scratch ----------------
#define LWF 16777216               // 8192*2048
#define WCATN 33554432             // 8192*4096
__device__ hf g_wcat[5 * WCATN];                     // enc l1,l2; dec l0,l1,l2  [Whh|Wih]
__device__ hf g_ewhh0[LWF];
__device__ hf g_ewih0[LWF];
__device__ hf g_fc1w[4194304], g_fc2w[2097152];
__device__ hf g_fd1w[2097152], g_fd2w[4194304];
__device__ hf g_xh[4194304];
__device__ hf g_f1a[1048576];
__device__ hf g_f2a[2097152];
__device__ hf g_d1a[65536];                          // [64,1024]
__device__ hf g_hH[6 * HB];                          // [layer][parity]
__device__ float g_pre[16 * 524288];
__device__ float g_c[3 * HB];
__device__ unsigned g_bar[8];      // [2]cnt,[3]gen (head group) [5]headdone
__device__ unsigned g_arr[64];     // per-phase arrival counters

// ===========================================================================
// prepass kernels
// ===========================================================================
struct SplitArgs {
    const float* s[6];
    hf* h[6];
    long off4[7];
};

__global__ void __launch_bounds__(256) split_all(SplitArgs a)
{
    const long total = a.off4[6];
    for (long v = (long)blockIdx.x * 256 + threadIdx.x; v < total;
         v += (long)gridDim.x * 256) {
        int seg = 0;
#pragma unroll
        for (int i = 0; i < 5; i++) seg += (v >= a.off4[i + 1]) ? 1 : 0;
        long e = (v - a.off4[seg]) * 4;
        float4 x = *(const float4*)(a.s[seg] + e);
        hf h0 = __float2half_rn(x.x), h1 = __float2half_rn(x.y);
        hf h2 = __float2half_rn(x.z), h3 = __float2half_rn(x.w);
        uint2 ph;
        ph.x = (uint32_t)*(uint16_t*)&h0 | ((uint32_t)*(uint16_t*)&h1 << 16);
        ph.y = (uint32_t)*(uint16_t*)&h2 | ((uint32_t)*(uint16_t*)&h3 << 16);
        *(uint2*)(a.h[seg] + e) = ph;
    }
}

// pack [Whh | Wih] (recurrent K first), gate-interleaved rows
__global__ void __launch_bounds__(256) lstm_pack(
    const float* __restrict__ wih, const float* __restrict__ whh,
    hf* __restrict__ dst, int hasx)
{
    const int K = hasx ? 4096 : 2048;
    const long total = (long)8192 * K / 4;
    for (long v = (long)blockIdx.x * 256 + threadIdx.x; v < total;
         v += (long)gridDim.x * 256) {
        int r = (int)(v / (K >> 2));
        int c = (int)(v % (K >> 2)) * 4;
        int gate = (r >> 4) & 3, jblk = r >> 6, jin = r & 15;
        int orig = gate * 2048 + jblk * 16 + jin;
        const float* src = (c < 2048)
            ? whh + (size_t)orig * 2048 + c
            : wih + (size_t)orig * 2048 + (c - 2048);
        float4 x = *(const float4*)src;
        hf h0 = __float2half_rn(x.x), h1 = __float2half_rn(x.y);
        hf h2 = __float2half_rn(x.z), h3 = __float2half_rn(x.w);
        uint2 ph;
        ph.x = (uint32_t)*(uint16_t*)&h0 | ((uint32_t)*(uint16_t*)&h1 << 16);
        ph.y = (uint32_t)*(uint16_t*)&h2 | ((uint32_t)*(uint16_t*)&h3 << 16);
        *(uint2*)(dst + (size_t)r * K + c) = ph;
    }
}

// ===========================================================================
// A-prefetch for next phase's chunks 0,1 (stages 0,1 A-regions)
// ===========================================================================
__device__ __forceinline__ void gemm_prefA(const hf* __restrict__ W, int K,
                                           uint32_t sb)
{
    const int t = threadIdx.x;
    const int r0 = t >> 4, seg = t & 15;
#pragma unroll
    for (int chunk = 0; chunk < 2; chunk++) {
        const uint32_t st = sb + chunk * STAGE;
#pragma unroll
        for (int i = 0; i < 4; i++) {
            int row = r0 + i * 16;
            cpa(st + row * ROWB + seg * 16 + OFF_A,
                W + (size_t)row * K + (chunk << 7) + seg * 8);
        }
        cpcommit();
    }
}

// ===========================================================================
// 1-term GEMM mainloop, K-chunks of 128, 4 stages.
// Segments: B1 (cols 0..K1-1, ready at entry), B2 (cols K1.., needs wflag).
// wflag: deferred wait — spin until *wflag >= wtarget just before issuing
// the first B2 chunk (hidden behind B1-half compute).
// ===========================================================================
__device__ __forceinline__ void run_gemm(
    const hf* __restrict__ W, int K,
    const hf* __restrict__ B1, int K1, int ldb1,
    const hf* __restrict__ B2, int ldb2,
    uint32_t sb, float acc[2][2][4], int preA,
    const unsigned* wflag, unsigned wtarget)
{
    const int t = threadIdx.x;
    const int NC = K >> 7;
    const int xs = K1 >> 7;
    const int r0 = t >> 4, seg = t & 15;

    auto bsrc = [&](int kg, const hf*& b, int& ks, int& ldb) {
        if (kg < K1) { b = B1; ks = kg; ldb = ldb1; }
        else         { b = B2; ks = kg - K1; ldb = ldb2; }
    };
    auto issueAB = [&](int chunk) {
        if (chunk < NC) {
            const uint32_t st = sb + (chunk & 3) * STAGE;
            const int kg = chunk << 7;
            const hf* b; int ks, ldb;
            bsrc(kg, b, ks, ldb);
#pragma unroll
            for (int i = 0; i < 4; i++) {
                int row = r0 + i * 16;
                uint32_t dd = st + row * ROWB + seg * 16;
                cpa(dd + OFF_A, W + (size_t)row * K   + kg + seg * 8);
                cpa(dd + OFF_B, b + (size_t)row * ldb + ks + seg * 8);
            }
        }
        cpcommit();
    };
    auto issueB = [&](int chunk) {
        const uint32_t st = sb + (chunk & 3) * STAGE;
        const int kg = chunk << 7;
        const hf* b; int ks, ldb;
        bsrc(kg, b, ks, ldb);
#pragma unroll
        for (int i = 0; i < 4; i++) {
            int row = r0 + i * 16;
            cpa(st + row * ROWB + seg * 16 + OFF_B,
                b + (size_t)row * ldb + ks + seg * 8);
        }
        cpcommit();
    };

    if (preA) {
        issueB(0); issueB(1); issueAB(2);
    } else {
        __syncthreads();
        issueAB(0); issueAB(1); issueAB(2);
    }

    const int w = t >> 5, lane = t & 31;
    const int moff = (w & 1) * 32, noff = (w >> 1) * 16;
    const int arow = lane & 15, ahalf = lane >> 4;
    const int bj = lane >> 3;
    const int brow = ((bj >> 1) * 8) + (lane & 7), bkh = bj & 1;

#pragma unroll
    for (int mi = 0; mi < 2; mi++)
#pragma unroll
        for (int nj = 0; nj < 2; nj++)
#pragma unroll
            for (int q = 0; q < 4; q++) acc[mi][nj][q] = 0.f;

    for (int s = 0; s < NC; s++) {
        cpwait<2>();
        __syncthreads();
        const uint32_t st = sb + (s & 3) * STAGE;
#pragma unroll
        for (int k16 = 0; k16 < 8; k16++) {
            const int kb = k16 * 32;
            uint32_t ah[2][4], bb[4];
#pragma unroll
            for (int mi = 0; mi < 2; mi++) {
                uint32_t ra = (uint32_t)((moff + mi * 16 + arow) * ROWB + kb + ahalf * 16);
                LDSM4(ah[mi], st + OFF_A + ra);
            }
            uint32_t rb = (uint32_t)((noff + brow) * ROWB + kb + bkh * 16);
            LDSM4(bb, st + OFF_B + rb);
#pragma unroll
            for (int mi = 0; mi < 2; mi++)
#pragma unroll
                for (int nj = 0; nj < 2; nj++)
                    MMA(acc[mi][nj], ah[mi], bb[nj * 2], bb[nj * 2 + 1]);
        }
        if (wflag && s + 3 == xs) {
            if (t == 0)
                while (*(volatile const unsigned*)wflag < wtarget) __nanosleep(64);
            __syncthreads();
        }
        issueAB(s + 3);
    }
}

__device__ __forceinline__ void stage_cs(float acc[2][2][4], float* cs)
{
    const int t = threadIdx.x;
    const int w = t >> 5, lane = t & 31;
    const int moff = (w & 1) * 32, noff = (w >> 1) * 16;
    const int rr = lane >> 2, cc = (lane & 3) * 2;
    __syncthreads();
#pragma unroll
    for (int mi = 0; mi < 2; mi++)
#pragma unroll
        for (int nj = 0; nj < 2; nj++) {
            int m = moff + mi * 16 + rr;
            int n = noff + nj * 8 + cc;
            cs[n * 68 + m]           = acc[mi][nj][0];
            cs[(n + 1) * 68 + m]     = acc[mi][nj][1];
            cs[n * 68 + m + 8]       = acc[mi][nj][2];
            cs[(n + 1) * 68 + m + 8] = acc[mi][nj][3];
        }
    __syncthreads();
}

__device__ __forceinline__ void barx(unsigned* cnt, unsigned* gen,
                                     unsigned& mygen, unsigned total)
{
    __threadfence();
    __syncthreads();
    if (threadIdx.x == 0) {
        mygen += 1;
        unsigned prev = atomicAdd(cnt, 1u);
        if (prev == total - 1) {
            atomicExch(cnt, 0u);
            __threadfence();
            atomicExch(gen, mygen);
        } else {
            while (atomicAdd(gen, 0u) < mygen) __nanosleep(64);
            __threadfence();
        }
    }
    __syncthreads();
}

// ===========================================================================
// batched FC GEMM (prepass-stage)
// ===========================================================================
__global__ void __launch_bounds__(256)
gemm_ms(const hf* __restrict__ A0, const hf* __restrict__ B0,
        const float* __restrict__ bias,
        float* __restrict__ outf, hf* __restrict__ outh,
        int K, int ldc, int dual)
{
    extern __shared__ char smem[];
    const uint32_t sb = (uint32_t)__cvta_generic_to_shared(smem);
    const int t = threadIdx.x;
    const int fbase = blockIdx.x * TM;
    const int nbase = blockIdx.y * 64;

    float acc[2][2][4];
    run_gemm(A0 + (size_t)fbase * K, K,
             B0 + (size_t)nbase * K, K, K, nullptr, 0, sb, acc, 0, nullptr, 0);

    const int w = t >> 5, lane = t & 31;
    const int moff = (w & 1) * 32, noff = (w >> 1) * 16;
    const int rr = lane >> 2, cc = (lane & 3) * 2;

    if (dual == 2) {
        float* po = outf + (size_t)blockIdx.y * 524288;
#pragma unroll
        for (int mi = 0; mi < 2; mi++)
#pragma unroll
            for (int nj = 0; nj < 2; nj++) {
                int m = moff + mi * 16 + rr;
                int n = noff + nj * 8 + cc;
                *(float2*)(po + (size_t)(fbase + m) * 64 + n) =
                    make_float2(acc[mi][nj][0], acc[mi][nj][1]);
                *(float2*)(po + (size_t)(fbase + m + 8) * 64 + n) =
                    make_float2(acc[mi][nj][2], acc[mi][nj][3]);
            }
        return;
    }

    float* cs = (float*)(smem + CS_OFF);
    stage_cs(acc, cs);
    const int b = t >> 2, j0 = (t & 3) * 16;
    const float* bp = bias + fbase + j0;
    hf* dh = outh + (size_t)(nbase + b) * ldc + fbase + j0;
#pragma unroll
    for (int j = 0; j < 16; j++) {
        float v = fmaxf(cs[b * 68 + j0 + j] + bp[j], 0.f);
        dh[j] = __float2half_rn(v);
    }
}

// ===========================================================================
// persistent kernels
// ===========================================================================
struct PP {
    const hf *wcat, *ewhh0;
    const float *pre, *en_b, *de_b;
    hf *hH;
    float *c;
    const hf *fd1w, *fd2w;
    const float *fd1b, *fd2b;
    hf *d1a;
    float *out;
    unsigned *bar;
    unsigned *arr;
};

__device__ __forceinline__ void lstm_cell_epi(
    float acc[2][2][4], float* cs, const float* pre, const float* bias,
    float* c, hf* hh, int jg0)
{
    stage_cs(acc, cs);
    const int t = threadIdx.x;
    const int b = t >> 2, j4 = (t & 3) * 4;
    float4 cold = *(const float4*)(c + (size_t)b * 2048 + jg0 + j4);
    float cn[4]; hf hi4[4];
#pragma unroll
    for (int q = 0; q < 4; q++) {
        const int j = j4 + q, jg = jg0 + j;
        float iv = cs[b * 68 + j];
        float fv = cs[b * 68 + 16 + j];
        float gv = cs[b * 68 + 32 + j];
        float ov = cs[b * 68 + 48 + j];
        if (pre) {
            iv += pre[(size_t)(jg) * 64 + b];
            fv += pre[(size_t)(2048 + jg) * 64 + b];
            gv += pre[(size_t)(4096 + jg) * 64 + b];
            ov += pre[(size_t)(6144 + jg) * 64 + b];
        }
        iv += bias[jg]; fv += bias[2048 + jg];
        gv += bias[4096 + jg]; ov += bias[6144 + jg];
        float si = 1.f / (1.f + __expf(-iv));
        float sf = 1.f / (1.f + __expf(-fv));
        float so = 1.f / (1.f + __expf(-ov));
        float c2 = sf * (&cold.x)[q] + si * tanhf(gv);
        float h2 = so * tanhf(c2);
        cn[q] = c2;
        hi4[q] = __float2half_rn(h2);
    }
    *(float4*)(c + (size_t)b * 2048 + jg0 + j4) = *(float4*)cn;
    *(uint2*)(hh + (size_t)b * 2048 + jg0 + j4) = *(uint2*)hi4;
}

// arrival: publish epilogue stores, bump per-phase counter
__device__ __forceinline__ void arrive(unsigned* a)
{
    __syncthreads();
    if (threadIdx.x == 0) { __threadfence(); atomicAdd(a, 1u); }
}

__global__ void __launch_bounds__(256)
enc_persist(PP p)
{
    extern __shared__ char smem[];
    const uint32_t sb = (uint32_t)__cvta_generic_to_shared(smem);
    float* cs = (float*)(smem + CS_OFF);
    const int bid = blockIdx.x;
    const int fbase = bid * TM, jg0 = bid * 16;
    float acc[2][2][4];
    auto HHp = [&](int l, int pr) { return p.hH + (size_t)(l * 2 + pr) * HB; };
    const hf* w0 = p.ewhh0 + (size_t)fbase * 2048;
    const hf* w1 = p.wcat + (size_t)0 * WCATN + (size_t)fbase * 4096;
    const hf* w2 = p.wcat + (size_t)1 * WCATN + (size_t)fbase * 4096;

    for (int t16 = 0; t16 < 16; t16++) {
        const int rp = t16 & 1, wp = 1 - rp;
        // l0: Whh-only (K=2048), no wait; pre-gates added in epilogue
        run_gemm(w0, 2048, HHp(0, rp), 2048, 2048, nullptr, 0,
                 sb, acc, t16 > 0, nullptr, 0);
        gemm_prefA(w1, 4096, sb);
        lstm_cell_epi(acc, cs, p.pre + (size_t)t16 * 524288, p.en_b,
                      p.c, HHp(0, wp), jg0);
        arrive(p.arr + 3 * t16);

        // l1: [Whh·h1(rp) | Wih·h0(wp)], deferred wait on l0 arrivals
        run_gemm(w1, 4096, HHp(1, rp), 2048, 2048, HHp(0, wp), 2048,
                 sb, acc, 1, p.arr + 3 * t16, NCTA);
        gemm_prefA(w2, 4096, sb);
        lstm_cell_epi(acc, cs, nullptr, p.en_b + 8192,
                      p.c + HB, HHp(1, wp), jg0);
        arrive(p.arr + 3 * t16 + 1);

        // l2
        run_gemm(w2, 4096, HHp(2, rp), 2048, 2048, HHp(1, wp), 2048,
                 sb, acc, 1, p.arr + 3 * t16 + 1, NCTA);
        if (t16 < 15) gemm_prefA(w0, 2048, sb);
        lstm_cell_epi(acc, cs, nullptr, p.en_b + 16384,
                      p.c + 2 * HB, HHp(2, wp), jg0);
        arrive(p.arr + 3 * t16 + 2);
    }
}

__global__ void __launch_bounds__(256)
dec_persist(PP p)
{
    extern __shared__ char smem[];
    const uint32_t sb = (uint32_t)__cvta_generic_to_shared(smem);
    float* cs = (float*)(smem + CS_OFF);
    const int bid = blockIdx.x;
    float acc[2][2][4];
    auto HHp = [&](int l, int pr) { return p.hH + (size_t)(l * 2 + pr) * HB; };

    if (bid < NCTA) {
        const int fbase = bid * TM, jg0 = bid * 16;
        const hf* w0 = p.wcat + (size_t)2 * WCATN + (size_t)fbase * 4096;
        const hf* w1 = p.wcat + (size_t)3 * WCATN + (size_t)fbase * 4096;
        const hf* w2 = p.wcat + (size_t)4 * WCATN + (size_t)fbase * 4096;
        for (int t16 = 0; t16 < 16; t16++) {
            const int rp = t16 & 1, wp = 1 - rp;
            // l0: [Whh·h0(rp) | Wih·h2(rp)]; wait = l2 of prev step
            run_gemm(w0, 4096, HHp(0, rp), 2048, 2048, HHp(2, rp), 2048,
                     sb, acc, t16 > 0,
                     t16 > 0 ? p.arr + 3 * t16 - 1 : nullptr, NCTA);
            gemm_prefA(w1, 4096, sb);
            lstm_cell_epi(acc, cs, nullptr, p.de_b, p.c, HHp(0, wp), jg0);
            arrive(p.arr + 3 * t16);

            run_gemm(w1, 4096, HHp(1, rp), 2048, 2048, HHp(0, wp), 2048,
                     sb, acc, 1, p.arr + 3 * t16, NCTA);
            gemm_prefA(w2, 4096, sb);
            lstm_cell_epi(acc, cs, nullptr, p.de_b + 8192,
                          p.c + HB, HHp(1, wp), jg0);
            arrive(p.arr + 3 * t16 + 1);

            run_gemm(w2, 4096, HHp(2, rp), 2048, 2048, HHp(1, wp), 2048,
                     sb, acc, 1, p.arr + 3 * t16 + 1, NCTA);
            if (t16 < 15) gemm_prefA(w0, 4096, sb);
            // before epilogue overwrites h2(wp) (head reads step t16-2's h2):
            if (t16 >= 2 && threadIdx.x == 0)
                while (*(volatile unsigned*)(p.bar + 5) < (unsigned)(t16 - 1))
                    __nanosleep(64);
            lstm_cell_epi(acc, cs, nullptr, p.de_b + 16384,
                          p.c + 2 * HB, HHp(2, wp), jg0);
            arrive(p.arr + 3 * t16 + 2);
        }
    } else {
        const int hbid = bid - NCTA;   // 0..NHEAD-1
        unsigned hgen = 0;
        for (int t16 = 0; t16 < 16; t16++) {
            // wait: h2(t16) ready (all l2 arrivals)
            if (threadIdx.x == 0)
                while (*(volatile unsigned*)(p.arr + 3 * t16 + 2) < NCTA)
                    __nanosleep(128);
            __syncthreads();
            __threadfence();
            const int wp = 1 - (t16 & 1);
            if (hbid < 16) {
                const int fbase = hbid * TM;
                run_gemm(p.fd1w + (size_t)fbase * 2048, 2048,
                         HHp(2, wp), 2048, 2048, nullptr, 0,
                         sb, acc, 0, nullptr, 0);
                stage_cs(acc, cs);
                const int t = threadIdx.x;
                const int b = t >> 2, j0 = (t & 3) * 16;
                const float* bp = p.fd1b + fbase + j0;
                hf* dh = p.d1a + (size_t)b * 1024 + fbase + j0;
#pragma unroll
                for (int j = 0; j < 16; j++) {
                    float v = fmaxf(cs[b * 68 + j0 + j] + bp[j], 0.f);
                    dh[j] = __float2half_rn(v);
                }
            }
            barx(p.bar + 2, p.bar + 3, hgen, NHEAD);
            if (hbid == 0 && threadIdx.x == 0)
                atomicExch(p.bar + 5, (unsigned)(t16 + 1));   // h2(t16) consumed
            for (int idx = hbid; idx < 64; idx += NHEAD) {
                const int f2 = idx * TM;
                run_gemm(p.fd2w + (size_t)f2 * 1024, 1024,
                         p.d1a, 1024, 1024, nullptr, 0, sb, acc, 0, nullptr, 0);
                stage_cs(acc, cs);
                const int t = threadIdx.x;
                const int b = t >> 2, j0 = (t & 3) * 16;
                const float* bp = p.fd2b + f2 + j0;
                float* dst = p.out + (size_t)t16 * 262144 + (size_t)b * 4096 + f2 + j0;
#pragma unroll
                for (int j = 0; j < 16; j++) {
                    float v = cs[b * 68 + j0 + j] + bp[j];
                    dst[j] = 1.f / (1.f + __expf(-v));
                }
            }
            barx(p.bar + 2, p.bar + 3, hgen, NHEAD);   // d1a free before next fd1
        }
    }
}

extern "C" void kernel_launch(void* const* d_in, const int* in_sizes, int n_in,
                              void* d_out, int out_size)
{
    const float* x        = (const float*)d_in[0];
    const float* fc_en1_w = (const float*)d_in[1];
    const float* fc_en1_b = (const float*)d_in[2];
    const float* fc_en2_w = (const float*)d_in[3];
    const float* fc_en2_b = (const float*)d_in[4];
    const float* en_wih   = (const float*)d_in[5];
    const float* en_whh   = (const float*)d_in[6];
    const float* en_b     = (const float*)d_in[7];
    const float* de_wih   = (const float*)d_in[8];
    const float* de_whh   = (const float*)d_in[9];
    const float* de_b     = (const float*)d_in[10];
    const float* fc_de1_w = (const float*)d_in[11];
    const float* fc_de1_b = (const float*)d_in[12];
    const float* fc_de2_w = (const float*)d_in[13];
    const float* fc_de2_b = (const float*)d_in[14];
    float* out = (float*)d_out;

    hf *wcat, *ewhh0, *ewih0, *fc1w, *fc2w, *fd1w, *fd2w;
    hf *xh, *f1a, *f2a, *d1a, *hH;
    float *pre, *c;
    unsigned *bar, *arr;
    cudaGetSymbolAddress((void**)&wcat, g_wcat);
    cudaGetSymbolAddress((void**)&ewhh0, g_ewhh0);
    cudaGetSymbolAddress((void**)&ewih0, g_ewih0);
    cudaGetSymbolAddress((void**)&fc1w, g_fc1w);  cudaGetSymbolAddress((void**)&fc2w, g_fc2w);
    cudaGetSymbolAddress((void**)&fd1w, g_fd1w);  cudaGetSymbolAddress((void**)&fd2w, g_fd2w);
    cudaGetSymbolAddress((void**)&xh, g_xh);
    cudaGetSymbolAddress((void**)&f1a, g_f1a);    cudaGetSymbolAddress((void**)&f2a, g_f2a);
    cudaGetSymbolAddress((void**)&d1a, g_d1a);    cudaGetSymbolAddress((void**)&hH, g_hH);
    cudaGetSymbolAddress((void**)&pre, g_pre);    cudaGetSymbolAddress((void**)&c, g_c);
    cudaGetSymbolAddress((void**)&bar, g_bar);    cudaGetSymbolAddress((void**)&arr, g_arr);

    cudaFuncSetAttribute(gemm_ms,     cudaFuncAttributeMaxDynamicSharedMemorySize, SMEM_SZ);
    cudaFuncSetAttribute(enc_persist, cudaFuncAttributeMaxDynamicSharedMemorySize, SMEM_SZ);
    cudaFuncSetAttribute(dec_persist, cudaFuncAttributeMaxDynamicSharedMemorySize, SMEM_SZ);

    auto HHp = [&](int l, int pr) { return hH + (size_t)(l * 2 + pr) * HB; };

    // ---- prepass ----
    {
        SplitArgs a;
        const float* srcs[6] = {en_wih, fc_en1_w, fc_en2_w, fc_de1_w, fc_de2_w, x};
        hf* hs[6] = {ewih0, fc1w, fc2w, fd1w, fd2w, xh};
        long ns[6] = {LWF, 4194304, 2097152, 2097152, 4194304, 4194304};
        long acc = 0;
        for (int i = 0; i < 6; i++) {
            a.s[i] = srcs[i]; a.h[i] = hs[i];
            a.off4[i] = acc; acc += ns[i] / 4;
        }
        a.off4[6] = acc;
        split_all<<<1024, 256>>>(a);
    }
    lstm_pack<<<2048, 256>>>(en_wih + (size_t)1 * LWF, en_whh + (size_t)1 * LWF,
                             wcat + (size_t)0 * WCATN, 1);
    lstm_pack<<<2048, 256>>>(en_wih + (size_t)2 * LWF, en_whh + (size_t)2 * LWF,
                             wcat + (size_t)1 * WCATN, 1);
    lstm_pack<<<2048, 256>>>(de_wih,                   de_whh,
                             wcat + (size_t)2 * WCATN, 1);
    lstm_pack<<<2048, 256>>>(de_wih + (size_t)1 * LWF, de_whh + (size_t)1 * LWF,
                             wcat + (size_t)3 * WCATN, 1);
    lstm_pack<<<2048, 256>>>(de_wih + (size_t)2 * LWF, de_whh + (size_t)2 * LWF,
                             wcat + (size_t)4 * WCATN, 1);
    lstm_pack<<<1024, 256>>>(nullptr, en_whh, ewhh0, 0);

    cudaMemsetAsync(hH, 0, 6 * HB * sizeof(hf));
    cudaMemsetAsync(c,  0, 3 * HB * sizeof(float));

    // ---- batched encoder FCs + l0 pre-gates ----
    gemm_ms<<<dim3(16, 16), 256, SMEM_SZ>>>(fc1w, xh, fc_en1_b,
        nullptr, f1a, 4096, 1024, 0);
    gemm_ms<<<dim3(32, 16), 256, SMEM_SZ>>>(fc2w, f1a, fc_en2_b,
        nullptr, f2a, 1024, 2048, 0);
    gemm_ms<<<dim3(128, 16), 256, SMEM_SZ>>>(ewih0, f2a, nullptr,
        pre, nullptr, 2048, 0, 2);

    PP p;
    p.wcat = wcat; p.ewhh0 = ewhh0; p.pre = pre;
    p.en_b = en_b; p.de_b = de_b;
    p.hH = hH; p.c = c;
    p.fd1w = fd1w; p.fd2w = fd2w; p.fd1b = fc_de1_b; p.fd2b = fc_de2_b;
    p.d1a = d1a; p.out = out; p.bar = bar; p.arr = arr;

    // ---- encoder ----
    cudaMemsetAsync(bar, 0, 8 * sizeof(unsigned));
    cudaMemsetAsync(arr, 0, 64 * sizeof(unsigned));
    enc_persist<<<NCTA, 256, SMEM_SZ>>>(p);

    // ---- decoder init: h0(p0) = enc h2(p0); h1,h2(p0) zero; c zero ----
    cudaMemcpyAsync(HHp(0, 0), HHp(2, 0), HB * sizeof(hf), cudaMemcpyDeviceToDevice);
    cudaMemsetAsync(HHp(1, 0), 0, HB * sizeof(hf));
    cudaMemsetAsync(HHp(2, 0), 0, HB * sizeof(hf));
    cudaMemsetAsync(c, 0, 3 * HB * sizeof(float));

    // ---- decoder (LSTM CTAs + concurrent head CTAs, one launch) ----
    cudaMemsetAsync(bar, 0, 8 * sizeof(unsigned));
    cudaMemsetAsync(arr, 0, 64 * sizeof(unsigned));
    dec_persist<<<NCTA + NHEAD, 256, SMEM_SZ>>>(p);
}

// round 16
// speedup vs baseline: 1.7613x; 1.0175x over previous
#include <cuda_runtime.h>
#include <cuda_fp16.h>
#include <cstdint>
#include <cstddef>

typedef __half hf;

// ---------------- tile constants ----------------
#define TM    64
#define ROWB  272                 // 256B row + 16B pad -> conflict-free ldmatrix
#define OFF_A  0
#define OFF_B  17408              // 64*272
#define STAGE  34816
#define NSTG   4
#define SMEM_SZ (NSTG * STAGE)    // 139264 B -> 1 CTA/SM
#define CS_OFF (3 * STAGE + OFF_B)  // epilogue staging (stage3 B half)
#define NCTA  128                 // LSTM CTAs
#define NHEAD 20                  // head CTAs
#define HB    131072              // 64*2048 elems

// ---------------- asm helpers ----------------
__device__ __forceinline__ void cpa(uint32_t d, const void* s) {
    asm volatile("cp.async.cg.shared.global [%0], [%1], 16;" :: "r"(d), "l"(s));
}
__device__ __forceinline__ void cpcommit() {
    asm volatile("cp.async.commit_group;" ::: "memory");
}
template <int N> __device__ __forceinline__ void cpwait() {
    asm volatile("cp.async.wait_group %0;" :: "n"(N) : "memory");
}
#define LDSM4(R, addr) \
    asm volatile("ldmatrix.sync.aligned.m8n8.x4.shared.b16 {%0,%1,%2,%3}, [%4];" \
        : "=r"((R)[0]), "=r"((R)[1]), "=r"((R)[2]), "=r"((R)[3]) : "r"(addr))
#define MMA(D, A, b0, b1) \
    asm volatile("mma.sync.aligned.m16n8k16.row.col.f32.f16.f16.f32 " \
        "{%0,%1,%2,%3}, {%4,%5,%6,%7}, {%8,%9}, {%0,%1,%2,%3};" \
        : "+f"((D)[0]), "+f"((D)[1]), "+f"((D)[2]), "+f"((D)[3]) \
        : "r"((A)[0]), "r"((A)[1]), "r"((A)[2]), "r"((A)[3]), "r"(b0), "r"(b1))

// ---------------- scratch ----------------
#define LWF 16777216               // 8192*2048
#define WCATN 33554432             // 8192*4096
__device__ hf g_wcat[6 * WCATN];   // enc l0,l1,l2; dec l0,l1,l2  [Whh|Wih]
__device__ hf g_fc1w[4194304], g_fc2w[2097152];
__device__ hf g_fd1w[2097152], g_fd2w[4194304];
__device__ hf g_xh[4194304];                         // [16][64][4096]
__device__ hf g_f1a[65536];                          // [64,1024] (per-step, reused)
__device__ hf g_f2a[2097152];                        // [16][64,2048]
__device__ hf g_d1a[65536];                          // [64,1024]
__device__ hf g_hH[6 * HB];                          // [layer][parity]
__device__ float g_c[3 * HB];
__device__ unsigned g_bar[8];      // [2]cnt,[3]gen head group; [5]headdone; [6]f2done
__device__ unsigned g_arr[64];     // per-phase arrival counters

// ===========================================================================
// prepass: fp32 -> fp16 split (FC weights + x)
// ===========================================================================
struct SplitArgs {
    const float* s[5];
    hf* h[5];
    long off4[6];
};

__global__ void __launch_bounds__(256) split_all(SplitArgs a)
{
    const long total = a.off4[5];
    for (long v = (long)blockIdx.x * 256 + threadIdx.x; v < total;
         v += (long)gridDim.x * 256) {
        int seg = 0;
#pragma unroll
        for (int i = 0; i < 4; i++) seg += (v >= a.off4[i + 1]) ? 1 : 0;
        long e = (v - a.off4[seg]) * 4;
        float4 x = *(const float4*)(a.s[seg] + e);
        hf h0 = __float2half_rn(x.x), h1 = __float2half_rn(x.y);
        hf h2 = __float2half_rn(x.z), h3 = __float2half_rn(x.w);
        uint2 ph;
        ph.x = (uint32_t)*(uint16_t*)&h0 | ((uint32_t)*(uint16_t*)&h1 << 16);
        ph.y = (uint32_t)*(uint16_t*)&h2 | ((uint32_t)*(uint16_t*)&h3 << 16);
        *(uint2*)(a.h[seg] + e) = ph;
    }
}

// pack all 6 LSTM matrices: [Whh | Wih], gate-interleaved rows
struct PackArgs { const float* wih[6]; const float* whh[6]; hf* dst; };

__global__ void __launch_bounds__(256) pack_all(PackArgs a)
{
    const long per = (long)8192 * 1024;          // uint2 units per matrix (4096/4)
    const long total = 6 * per;
    for (long v = (long)blockIdx.x * 256 + threadIdx.x; v < total;
         v += (long)gridDim.x * 256) {
        int mat = (int)(v / per);
        long vv = v % per;
        int r = (int)(vv >> 10);
        int c = (int)(vv & 1023) * 4;
        int gate = (r >> 4) & 3, jblk = r >> 6, jin = r & 15;
        int orig = gate * 2048 + jblk * 16 + jin;
        const float* src = (c < 2048)
            ? a.whh[mat] + (size_t)orig * 2048 + c
            : a.wih[mat] + (size_t)orig * 2048 + (c - 2048);
        float4 x = *(const float4*)src;
        hf h0 = __float2half_rn(x.x), h1 = __float2half_rn(x.y);
        hf h2 = __float2half_rn(x.z), h3 = __float2half_rn(x.w);
        uint2 ph;
        ph.x = (uint32_t)*(uint16_t*)&h0 | ((uint32_t)*(uint16_t*)&h1 << 16);
        ph.y = (uint32_t)*(uint16_t*)&h2 | ((uint32_t)*(uint16_t*)&h3 << 16);
        *(uint2*)(a.dst + (size_t)mat * WCATN + (size_t)r * 4096 + c) = ph;
    }
}

// ===========================================================================
// A-prefetch for next phase's chunks 0,1
// ===========================================================================
__device__ __forceinline__ void gemm_prefA(const hf* __restrict__ W, int K,
                                           uint32_t sb)
{
    const int t = threadIdx.x;
    const int r0 = t >> 4, seg = t & 15;
#pragma unroll
    for (int chunk = 0; chunk < 2; chunk++) {
        const uint32_t st = sb + chunk * STAGE;
#pragma unroll
        for (int i = 0; i < 4; i++) {
            int row = r0 + i * 16;
            cpa(st + row * ROWB + seg * 16 + OFF_A,
                W + (size_t)row * K + (chunk << 7) + seg * 8);
        }
        cpcommit();
    }
}

// ===========================================================================
// 1-term GEMM mainloop, K-chunks of 128, 4 stages, deferred wflag wait
// before issuing the first B2 chunk.
// ===========================================================================
__device__ __forceinline__ void run_gemm(
    const hf* __restrict__ W, int K,
    const hf* __restrict__ B1, int K1, int ldb1,
    const hf* __restrict__ B2, int ldb2,
    uint32_t sb, float acc[2][2][4], int preA,
    const unsigned* wflag, unsigned wtarget)
{
    const int t = threadIdx.x;
    const int NC = K >> 7;
    const int xs = K1 >> 7;
    const int r0 = t >> 4, seg = t & 15;

    auto bsrc = [&](int kg, const hf*& b, int& ks, int& ldb) {
        if (kg < K1) { b = B1; ks = kg; ldb = ldb1; }
        else         { b = B2; ks = kg - K1; ldb = ldb2; }
    };
    auto issueAB = [&](int chunk) {
        if (chunk < NC) {
            const uint32_t st = sb + (chunk & 3) * STAGE;
            const int kg = chunk << 7;
            const hf* b; int ks, ldb;
            bsrc(kg, b, ks, ldb);
#pragma unroll
            for (int i = 0; i < 4; i++) {
                int row = r0 + i * 16;
                uint32_t dd = st + row * ROWB + seg * 16;
                cpa(dd + OFF_A, W + (size_t)row * K   + kg + seg * 8);
                cpa(dd + OFF_B, b + (size_t)row * ldb + ks + seg * 8);
            }
        }
        cpcommit();
    };
    auto issueB = [&](int chunk) {
        const uint32_t st = sb + (chunk & 3) * STAGE;
        const int kg = chunk << 7;
        const hf* b; int ks, ldb;
        bsrc(kg, b, ks, ldb);
#pragma unroll
        for (int i = 0; i < 4; i++) {
            int row = r0 + i * 16;
            cpa(st + row * ROWB + seg * 16 + OFF_B,
                b + (size_t)row * ldb + ks + seg * 8);
        }
        cpcommit();
    };

    if (preA) {
        issueB(0); issueB(1); issueAB(2);
    } else {
        __syncthreads();
        issueAB(0); issueAB(1); issueAB(2);
    }

    const int w = t >> 5, lane = t & 31;
    const int moff = (w & 1) * 32, noff = (w >> 1) * 16;
    const int arow = lane & 15, ahalf = lane >> 4;
    const int bj = lane >> 3;
    const int brow = ((bj >> 1) * 8) + (lane & 7), bkh = bj & 1;

#pragma unroll
    for (int mi = 0; mi < 2; mi++)
#pragma unroll
        for (int nj = 0; nj < 2; nj++)
#pragma unroll
            for (int q = 0; q < 4; q++) acc[mi][nj][q] = 0.f;

    for (int s = 0; s < NC; s++) {
        cpwait<2>();
        __syncthreads();
        const uint32_t st = sb + (s & 3) * STAGE;
#pragma unroll
        for (int k16 = 0; k16 < 8; k16++) {
            const int kb = k16 * 32;
            uint32_t ah[2][4], bb[4];
#pragma unroll
            for (int mi = 0; mi < 2; mi++) {
                uint32_t ra = (uint32_t)((moff + mi * 16 + arow) * ROWB + kb + ahalf * 16);
                LDSM4(ah[mi], st + OFF_A + ra);
            }
            uint32_t rb = (uint32_t)((noff + brow) * ROWB + kb + bkh * 16);
            LDSM4(bb, st + OFF_B + rb);
#pragma unroll
            for (int mi = 0; mi < 2; mi++)
#pragma unroll
                for (int nj = 0; nj < 2; nj++)
                    MMA(acc[mi][nj], ah[mi], bb[nj * 2], bb[nj * 2 + 1]);
        }
        if (wflag && s + 3 == xs) {
            if (t == 0)
                while (*(volatile const unsigned*)wflag < wtarget) __nanosleep(64);
            __syncthreads();
        }
        issueAB(s + 3);
    }
}

__device__ __forceinline__ void stage_cs(float acc[2][2][4], float* cs)
{
    const int t = threadIdx.x;
    const int w = t >> 5, lane = t & 31;
    const int moff = (w & 1) * 32, noff = (w >> 1) * 16;
    const int rr = lane >> 2, cc = (lane & 3) * 2;
    __syncthreads();
#pragma unroll
    for (int mi = 0; mi < 2; mi++)
#pragma unroll
        for (int nj = 0; nj < 2; nj++) {
            int m = moff + mi * 16 + rr;
            int n = noff + nj * 8 + cc;
            cs[n * 68 + m]           = acc[mi][nj][0];
            cs[(n + 1) * 68 + m]     = acc[mi][nj][1];
            cs[n * 68 + m + 8]       = acc[mi][nj][2];
            cs[(n + 1) * 68 + m + 8] = acc[mi][nj][3];
        }
    __syncthreads();
}

__device__ __forceinline__ void barx(unsigned* cnt, unsigned* gen,
                                     unsigned& mygen, unsigned total)
{
    __threadfence();
    __syncthreads();
    if (threadIdx.x == 0) {
        mygen += 1;
        unsigned prev = atomicAdd(cnt, 1u);
        if (prev == total - 1) {
            atomicExch(cnt, 0u);
            __threadfence();
            atomicExch(gen, mygen);
        } else {
            while (atomicAdd(gen, 0u) < mygen) __nanosleep(64);
            __threadfence();
        }
    }
    __syncthreads();
}

// ===========================================================================
// persistent kernels
// ===========================================================================
struct PP {
    const hf *wcat;
    const float *en_b, *de_b;
    hf *hH;
    float *c;
    const hf *fc1w, *fc2w, *fd1w, *fd2w;
    const float *fc1b, *fc2b, *fd1b, *fd2b;
    const hf *xh;
    hf *f1a, *f2a, *d1a;
    float *out;
    unsigned *bar;
    unsigned *arr;
};

__device__ __forceinline__ void lstm_cell_epi(
    float acc[2][2][4], float* cs, const float* bias,
    float* c, hf* hh, int jg0)
{
    stage_cs(acc, cs);
    const int t = threadIdx.x;
    const int b = t >> 2, j4 = (t & 3) * 4;
    float4 cold = *(const float4*)(c + (size_t)b * 2048 + jg0 + j4);
    float cn[4]; hf hi4[4];
#pragma unroll
    for (int q = 0; q < 4; q++) {
        const int j = j4 + q, jg = jg0 + j;
        float iv = cs[b * 68 + j]      + bias[jg];
        float fv = cs[b * 68 + 16 + j] + bias[2048 + jg];
        float gv = cs[b * 68 + 32 + j] + bias[4096 + jg];
        float ov = cs[b * 68 + 48 + j] + bias[6144 + jg];
        float si = 1.f / (1.f + __expf(-iv));
        float sf = 1.f / (1.f + __expf(-fv));
        float so = 1.f / (1.f + __expf(-ov));
        float c2 = sf * (&cold.x)[q] + si * tanhf(gv);
        float h2 = so * tanhf(c2);
        cn[q] = c2;
        hi4[q] = __float2half_rn(h2);
    }
    *(float4*)(c + (size_t)b * 2048 + jg0 + j4) = *(float4*)cn;
    *(uint2*)(hh + (size_t)b * 2048 + jg0 + j4) = *(uint2*)hi4;
}

__device__ __forceinline__ void arrive(unsigned* a)
{
    __syncthreads();
    if (threadIdx.x == 0) { __threadfence(); atomicAdd(a, 1u); }
}

// relu epilogue helper: cs -> fp16 out[b][ld] + bias
__device__ __forceinline__ void relu_epi(float* cs, const float* bias, int fbase,
                                         hf* outp, int ld)
{
    const int t = threadIdx.x;
    const int b = t >> 2, j0 = (t & 3) * 16;
    const float* bp = bias + fbase + j0;
    hf* dh = outp + (size_t)b * ld + fbase + j0;
#pragma unroll
    for (int j = 0; j < 16; j++) {
        float v = fmaxf(cs[b * 68 + j0 + j] + bp[j], 0.f);
        dh[j] = __float2half_rn(v);
    }
}

__global__ void __launch_bounds__(256)
enc_persist(PP p)
{
    extern __shared__ char smem[];
    const uint32_t sb = (uint32_t)__cvta_generic_to_shared(smem);
    float* cs = (float*)(smem + CS_OFF);
    const int bid = blockIdx.x;
    float acc[2][2][4];
    auto HHp = [&](int l, int pr) { return p.hH + (size_t)(l * 2 + pr) * HB; };

    if (bid < NCTA) {
        const int fbase = bid * TM, jg0 = bid * 16;
        const hf* w0 = p.wcat + (size_t)0 * WCATN + (size_t)fbase * 4096;
        const hf* w1 = p.wcat + (size_t)1 * WCATN + (size_t)fbase * 4096;
        const hf* w2 = p.wcat + (size_t)2 * WCATN + (size_t)fbase * 4096;

        for (int t16 = 0; t16 < 16; t16++) {
            const int rp = t16 & 1, wp = 1 - rp;
            // l0: [Whh·h0(rp) | Wih·f2a(t16)], deferred wait on f2done
            run_gemm(w0, 4096, HHp(0, rp), 2048, 2048,
                     p.f2a + (size_t)t16 * HB, 2048,
                     sb, acc, t16 > 0, p.bar + 6, (unsigned)(t16 + 1));
            gemm_prefA(w1, 4096, sb);
            lstm_cell_epi(acc, cs, p.en_b, p.c, HHp(0, wp), jg0);
            arrive(p.arr + 3 * t16);

            run_gemm(w1, 4096, HHp(1, rp), 2048, 2048, HHp(0, wp), 2048,
                     sb, acc, 1, p.arr + 3 * t16, NCTA);
            gemm_prefA(w2, 4096, sb);
            lstm_cell_epi(acc, cs, p.en_b + 8192, p.c + HB, HHp(1, wp), jg0);
            arrive(p.arr + 3 * t16 + 1);

            run_gemm(w2, 4096, HHp(2, rp), 2048, 2048, HHp(1, wp), 2048,
                     sb, acc, 1, p.arr + 3 * t16 + 1, NCTA);
            if (t16 < 15) gemm_prefA(w0, 4096, sb);
            lstm_cell_epi(acc, cs, p.en_b + 16384, p.c + 2 * HB, HHp(2, wp), jg0);
            arrive(p.arr + 3 * t16 + 2);
        }
    } else {
        // head CTAs: compute fc1/fc2 per step just-in-time
        const int hbid = bid - NCTA;
        unsigned hgen = 0;
        for (int t16 = 0; t16 < 16; t16++) {
            // fc1: 16 tiles, K=4096, B = x(t16)
            for (int idx = hbid; idx < 16; idx += NHEAD) {
                const int fbase = idx * TM;
                run_gemm(p.fc1w + (size_t)fbase * 4096, 4096,
                         p.xh + (size_t)t16 * 262144, 4096, 4096,
                         nullptr, 0, sb, acc, 0, nullptr, 0);
                stage_cs(acc, cs);
                relu_epi(cs, p.fc1b, fbase, p.f1a, 1024);
            }
            barx(p.bar + 2, p.bar + 3, hgen, NHEAD);
            // fc2: 32 tiles, K=1024, B = f1a
            for (int idx = hbid; idx < 32; idx += NHEAD) {
                const int fbase = idx * TM;
                run_gemm(p.fc2w + (size_t)fbase * 1024, 1024,
                         p.f1a, 1024, 1024, nullptr, 0, sb, acc, 0, nullptr, 0);
                stage_cs(acc, cs);
                relu_epi(cs, p.fc2b, fbase, p.f2a + (size_t)t16 * HB, 2048);
            }
            barx(p.bar + 2, p.bar + 3, hgen, NHEAD);
            if (hbid == 0 && threadIdx.x == 0)
                atomicExch(p.bar + 6, (unsigned)(t16 + 1));   // f2a(t16) ready
        }
    }
}

__global__ void __launch_bounds__(256)
dec_persist(PP p)
{
    extern __shared__ char smem[];
    const uint32_t sb = (uint32_t)__cvta_generic_to_shared(smem);
    float* cs = (float*)(smem + CS_OFF);
    const int bid = blockIdx.x;
    float acc[2][2][4];
    auto HHp = [&](int l, int pr) { return p.hH + (size_t)(l * 2 + pr) * HB; };

    if (bid < NCTA) {
        const int fbase = bid * TM, jg0 = bid * 16;
        const hf* w0 = p.wcat + (size_t)3 * WCATN + (size_t)fbase * 4096;
        const hf* w1 = p.wcat + (size_t)4 * WCATN + (size_t)fbase * 4096;
        const hf* w2 = p.wcat + (size_t)5 * WCATN + (size_t)fbase * 4096;
        for (int t16 = 0; t16 < 16; t16++) {
            const int rp = t16 & 1, wp = 1 - rp;
            run_gemm(w0, 4096, HHp(0, rp), 2048, 2048, HHp(2, rp), 2048,
                     sb, acc, t16 > 0,
                     t16 > 0 ? p.arr + 3 * t16 - 1 : nullptr, NCTA);
            gemm_prefA(w1, 4096, sb);
            lstm_cell_epi(acc, cs, p.de_b, p.c, HHp(0, wp), jg0);
            arrive(p.arr + 3 * t16);

            run_gemm(w1, 4096, HHp(1, rp), 2048, 2048, HHp(0, wp), 2048,
                     sb, acc, 1, p.arr + 3 * t16, NCTA);
            gemm_prefA(w2, 4096, sb);
            lstm_cell_epi(acc, cs, p.de_b + 8192, p.c + HB, HHp(1, wp), jg0);
            arrive(p.arr + 3 * t16 + 1);

            run_gemm(w2, 4096, HHp(2, rp), 2048, 2048, HHp(1, wp), 2048,
                     sb, acc, 1, p.arr + 3 * t16 + 1, NCTA);
            if (t16 < 15) gemm_prefA(w0, 4096, sb);
            if (t16 >= 2 && threadIdx.x == 0)
                while (*(volatile unsigned*)(p.bar + 5) < (unsigned)(t16 - 1))
                    __nanosleep(64);
            lstm_cell_epi(acc, cs, p.de_b + 16384, p.c + 2 * HB, HHp(2, wp), jg0);
            arrive(p.arr + 3 * t16 + 2);
        }
    } else {
        const int hbid = bid - NCTA;
        unsigned hgen = 0;
        for (int t16 = 0; t16 < 16; t16++) {
            if (threadIdx.x == 0)
                while (*(volatile unsigned*)(p.arr + 3 * t16 + 2) < NCTA)
                    __nanosleep(128);
            __syncthreads();
            __threadfence();
            const int wp = 1 - (t16 & 1);
            if (hbid < 16) {
                const int fbase = hbid * TM;
                run_gemm(p.fd1w + (size_t)fbase * 2048, 2048,
                         HHp(2, wp), 2048, 2048, nullptr, 0,
                         sb, acc, 0, nullptr, 0);
                stage_cs(acc, cs);
                relu_epi(cs, p.fd1b, fbase, p.d1a, 1024);
            }
            barx(p.bar + 2, p.bar + 3, hgen, NHEAD);
            if (hbid == 0 && threadIdx.x == 0)
                atomicExch(p.bar + 5, (unsigned)(t16 + 1));   // h2(t16) consumed
            for (int idx = hbid; idx < 64; idx += NHEAD) {
                const int f2 = idx * TM;
                run_gemm(p.fd2w + (size_t)f2 * 1024, 1024,
                         p.d1a, 1024, 1024, nullptr, 0, sb, acc, 0, nullptr, 0);
                stage_cs(acc, cs);
                const int t = threadIdx.x;
                const int b = t >> 2, j0 = (t & 3) * 16;
                const float* bp = p.fd2b + f2 + j0;
                float* dst = p.out + (size_t)t16 * 262144 + (size_t)b * 4096 + f2 + j0;
#pragma unroll
                for (int j = 0; j < 16; j++) {
                    float v = cs[b * 68 + j0 + j] + bp[j];
                    dst[j] = 1.f / (1.f + __expf(-v));
                }
            }
            barx(p.bar + 2, p.bar + 3, hgen, NHEAD);
        }
    }
}

extern "C" void kernel_launch(void* const* d_in, const int* in_sizes, int n_in,
                              void* d_out, int out_size)
{
    const float* x        = (const float*)d_in[0];
    const float* fc_en1_w = (const float*)d_in[1];
    const float* fc_en1_b = (const float*)d_in[2];
    const float* fc_en2_w = (const float*)d_in[3];
    const float* fc_en2_b = (const float*)d_in[4];
    const float* en_wih   = (const float*)d_in[5];
    const float* en_whh   = (const float*)d_in[6];
    const float* en_b     = (const float*)d_in[7];
    const float* de_wih   = (const float*)d_in[8];
    const float* de_whh   = (const float*)d_in[9];
    const float* de_b     = (const float*)d_in[10];
    const float* fc_de1_w = (const float*)d_in[11];
    const float* fc_de1_b = (const float*)d_in[12];
    const float* fc_de2_w = (const float*)d_in[13];
    const float* fc_de2_b = (const float*)d_in[14];
    float* out = (float*)d_out;

    hf *wcat, *fc1w, *fc2w, *fd1w, *fd2w;
    hf *xh, *f1a, *f2a, *d1a, *hH;
    float *c;
    unsigned *bar, *arr;
    cudaGetSymbolAddress((void**)&wcat, g_wcat);
    cudaGetSymbolAddress((void**)&fc1w, g_fc1w);  cudaGetSymbolAddress((void**)&fc2w, g_fc2w);
    cudaGetSymbolAddress((void**)&fd1w, g_fd1w);  cudaGetSymbolAddress((void**)&fd2w, g_fd2w);
    cudaGetSymbolAddress((void**)&xh, g_xh);
    cudaGetSymbolAddress((void**)&f1a, g_f1a);    cudaGetSymbolAddress((void**)&f2a, g_f2a);
    cudaGetSymbolAddress((void**)&d1a, g_d1a);    cudaGetSymbolAddress((void**)&hH, g_hH);
    cudaGetSymbolAddress((void**)&c, g_c);
    cudaGetSymbolAddress((void**)&bar, g_bar);    cudaGetSymbolAddress((void**)&arr, g_arr);

    cudaFuncSetAttribute(enc_persist, cudaFuncAttributeMaxDynamicSharedMemorySize, SMEM_SZ);
    cudaFuncSetAttribute(dec_persist, cudaFuncAttributeMaxDynamicSharedMemorySize, SMEM_SZ);

    auto HHp = [&](int l, int pr) { return hH + (size_t)(l * 2 + pr) * HB; };

    // ---- prepass: split (FC weights + x) and pack (6 LSTM cat matrices) ----
    {
        SplitArgs a;
        const float* srcs[5] = {fc_en1_w, fc_en2_w, fc_de1_w, fc_de2_w, x};
        hf* hs[5] = {fc1w, fc2w, fd1w, fd2w, xh};
        long ns[5] = {4194304, 2097152, 2097152, 4194304, 4194304};
        long acc = 0;
        for (int i = 0; i < 5; i++) {
            a.s[i] = srcs[i]; a.h[i] = hs[i];
            a.off4[i] = acc; acc += ns[i] / 4;
        }
        a.off4[5] = acc;
        split_all<<<1024, 256>>>(a);
    }
    {
        PackArgs a;
        a.wih[0] = en_wih;               a.whh[0] = en_whh;
        a.wih[1] = en_wih + (size_t)LWF; a.whh[1] = en_whh + (size_t)LWF;
        a.wih[2] = en_wih + 2*(size_t)LWF; a.whh[2] = en_whh + 2*(size_t)LWF;
        a.wih[3] = de_wih;               a.whh[3] = de_whh;
        a.wih[4] = de_wih + (size_t)LWF; a.whh[4] = de_whh + (size_t)LWF;
        a.wih[5] = de_wih + 2*(size_t)LWF; a.whh[5] = de_whh + 2*(size_t)LWF;
        a.dst = wcat;
        pack_all<<<4096, 256>>>(a);
    }

    cudaMemsetAsync(hH, 0, 6 * HB * sizeof(hf));
    cudaMemsetAsync(c,  0, 3 * HB * sizeof(float));
    cudaMemsetAsync(bar, 0, 8 * sizeof(unsigned));
    cudaMemsetAsync(arr, 0, 64 * sizeof(unsigned));

    PP p;
    p.wcat = wcat;
    p.en_b = en_b; p.de_b = de_b;
    p.hH = hH; p.c = c;
    p.fc1w = fc1w; p.fc2w = fc2w; p.fd1w = fd1w; p.fd2w = fd2w;
    p.fc1b = fc_en1_b; p.fc2b = fc_en2_b; p.fd1b = fc_de1_b; p.fd2b = fc_de2_b;
    p.xh = xh; p.f1a = f1a; p.f2a = f2a; p.d1a = d1a;
    p.out = out; p.bar = bar; p.arr = arr;

    // ---- encoder (LSTM CTAs + FC head CTAs, one launch) ----
    enc_persist<<<NCTA + NHEAD, 256, SMEM_SZ>>>(p);

    // ---- decoder init: h0(p0) = enc h2(p0); h1,h2(p0) zero; c zero ----
    cudaMemcpyAsync(HHp(0, 0), HHp(2, 0), HB * sizeof(hf), cudaMemcpyDeviceToDevice);
    cudaMemsetAsync(HHp(1, 0), 0, HB * sizeof(hf));
    cudaMemsetAsync(HHp(2, 0), 0, HB * sizeof(hf));
    cudaMemsetAsync(c, 0, 3 * HB * sizeof(float));
    cudaMemsetAsync(bar, 0, 8 * sizeof(unsigned));
    cudaMemsetAsync(arr, 0, 64 * sizeof(unsigned));

    // ---- decoder ----
    dec_persist<<<NCTA + NHEAD, 256, SMEM_SZ>>>(p);
}

// round 17
// speedup vs baseline: 1.9015x; 1.0796x over previous
#include <cuda_runtime.h>
#include <cuda_fp16.h>
#include <cstdint>
#include <cstddef>

typedef __half hf;

// ---------------- tile constants ----------------
#define TM    64
#define ROWB  272                 // 256B row + 16B pad -> conflict-free ldmatrix
#define OFF_A  0
#define OFF_B  17408              // 64*272
#define STAGE  34816
#define NSTG   4
#define SMEM_SZ (NSTG * STAGE)    // 139264 B -> 1 CTA/SM
#define CS_OFF (3 * STAGE + OFF_B)  // epilogue staging (stage3 B half)
#define NCTA  128                 // LSTM CTAs
#define NHEAD 20                  // head CTAs
#define HB    131072              // 64*2048 elems

// ---------------- asm helpers ----------------
__device__ __forceinline__ void cpa(uint32_t d, const void* s) {
    asm volatile("cp.async.cg.shared.global [%0], [%1], 16;" :: "r"(d), "l"(s));
}
__device__ __forceinline__ void cpcommit() {
    asm volatile("cp.async.commit_group;" ::: "memory");
}
template <int N> __device__ __forceinline__ void cpwait() {
    asm volatile("cp.async.wait_group %0;" :: "n"(N) : "memory");
}
#define LDSM4(R, addr) \
    asm volatile("ldmatrix.sync.aligned.m8n8.x4.shared.b16 {%0,%1,%2,%3}, [%4];" \
        : "=r"((R)[0]), "=r"((R)[1]), "=r"((R)[2]), "=r"((R)[3]) : "r"(addr))
#define MMA(D, A, b0, b1) \
    asm volatile("mma.sync.aligned.m16n8k16.row.col.f32.f16.f16.f32 " \
        "{%0,%1,%2,%3}, {%4,%5,%6,%7}, {%8,%9}, {%0,%1,%2,%3};" \
        : "+f"((D)[0]), "+f"((D)[1]), "+f"((D)[2]), "+f"((D)[3]) \
        : "r"((A)[0]), "r"((A)[1]), "r"((A)[2]), "r"((A)[3]), "r"(b0), "r"(b1))

// ---------------- scratch ----------------
#define LWF 16777216               // 8192*2048
#define WCATN 33554432             // 8192*4096
__device__ hf g_wcat[6 * WCATN];   // enc l0,l1,l2; dec l0,l1,l2  [Whh|Wih]
__device__ hf g_fc1w[4194304], g_fc2w[2097152];
__device__ hf g_fd1w[2097152], g_fd2w[4194304];
__device__ hf g_xh[4194304];                         // [16][64][4096]
__device__ hf g_f1a[65536];                          // [64,1024]
__device__ hf g_f2a[2097152];                        // [16][64,2048]
__device__ hf g_d1a[65536];                          // [64,1024]
__device__ hf g_hH[6 * HB];                          // [layer][parity]
__device__ float g_c[3 * HB];
__device__ unsigned g_bar[8];      // [2]cnt,[3]gen head group; [5]headdone; [6]f2done
__device__ unsigned g_arr[64];     // per-phase arrival counters

// ===========================================================================
// prepass: fp32 -> fp16 split (FC weights + x)
// ===========================================================================
struct SplitArgs {
    const float* s[5];
    hf* h[5];
    long off4[6];
};

__global__ void __launch_bounds__(256) split_all(SplitArgs a)
{
    const long total = a.off4[5];
    for (long v = (long)blockIdx.x * 256 + threadIdx.x; v < total;
         v += (long)gridDim.x * 256) {
        int seg = 0;
#pragma unroll
        for (int i = 0; i < 4; i++) seg += (v >= a.off4[i + 1]) ? 1 : 0;
        long e = (v - a.off4[seg]) * 4;
        float4 x = *(const float4*)(a.s[seg] + e);
        hf h0 = __float2half_rn(x.x), h1 = __float2half_rn(x.y);
        hf h2 = __float2half_rn(x.z), h3 = __float2half_rn(x.w);
        uint2 ph;
        ph.x = (uint32_t)*(uint16_t*)&h0 | ((uint32_t)*(uint16_t*)&h1 << 16);
        ph.y = (uint32_t)*(uint16_t*)&h2 | ((uint32_t)*(uint16_t*)&h3 << 16);
        *(uint2*)(a.h[seg] + e) = ph;
    }
}

// pack all 6 LSTM matrices: [Whh | Wih], gate-interleaved rows
struct PackArgs { const float* wih[6]; const float* whh[6]; hf* dst; };

__global__ void __launch_bounds__(256) pack_all(PackArgs a)
{
    const long per = (long)8192 * 1024;
    const long total = 6 * per;
    for (long v = (long)blockIdx.x * 256 + threadIdx.x; v < total;
         v += (long)gridDim.x * 256) {
        int mat = (int)(v / per);
        long vv = v % per;
        int r = (int)(vv >> 10);
        int c = (int)(vv & 1023) * 4;
        int gate = (r >> 4) & 3, jblk = r >> 6, jin = r & 15;
        int orig = gate * 2048 + jblk * 16 + jin;
        const float* src = (c < 2048)
            ? a.whh[mat] + (size_t)orig * 2048 + c
            : a.wih[mat] + (size_t)orig * 2048 + (c - 2048);
        float4 x = *(const float4*)src;
        hf h0 = __float2half_rn(x.x), h1 = __float2half_rn(x.y);
        hf h2 = __float2half_rn(x.z), h3 = __float2half_rn(x.w);
        uint2 ph;
        ph.x = (uint32_t)*(uint16_t*)&h0 | ((uint32_t)*(uint16_t*)&h1 << 16);
        ph.y = (uint32_t)*(uint16_t*)&h2 | ((uint32_t)*(uint16_t*)&h3 << 16);
        *(uint2*)(a.dst + (size_t)mat * WCATN + (size_t)r * 4096 + c) = ph;
    }
}

// ===========================================================================
// A-prefetch for next phase's chunks 0,1
// ===========================================================================
__device__ __forceinline__ void gemm_prefA(const hf* __restrict__ W, int K,
                                           uint32_t sb)
{
    const int t = threadIdx.x;
    const int r0 = t >> 4, seg = t & 15;
#pragma unroll
    for (int chunk = 0; chunk < 2; chunk++) {
        const uint32_t st = sb + chunk * STAGE;
#pragma unroll
        for (int i = 0; i < 4; i++) {
            int row = r0 + i * 16;
            cpa(st + row * ROWB + seg * 16 + OFF_A,
                W + (size_t)row * K + (chunk << 7) + seg * 8);
        }
        cpcommit();
    }
}

// ===========================================================================
// 1-term GEMM mainloop: K-chunks of 128, 4 stages, 32x32 warp tiles with
// chunk-parity split across the two warpgroups (wg0=even chunks, wg1=odd).
// acc[2][4][4]: mi(2 x m16) x nj(4 x n8) x 4.
// ===========================================================================
__device__ __forceinline__ void run_gemm(
    const hf* __restrict__ W, int K,
    const hf* __restrict__ B1, int K1, int ldb1,
    const hf* __restrict__ B2, int ldb2,
    uint32_t sb, float acc[2][4][4], int preA,
    const unsigned* wflag, unsigned wtarget)
{
    const int t = threadIdx.x;
    const int NC = K >> 7;
    const int xs = K1 >> 7;
    const int r0 = t >> 4, seg = t & 15;

    auto bsrc = [&](int kg, const hf*& b, int& ks, int& ldb) {
        if (kg < K1) { b = B1; ks = kg; ldb = ldb1; }
        else         { b = B2; ks = kg - K1; ldb = ldb2; }
    };
    auto issueAB = [&](int chunk) {
        if (chunk < NC) {
            const uint32_t st = sb + (chunk & 3) * STAGE;
            const int kg = chunk << 7;
            const hf* b; int ks, ldb;
            bsrc(kg, b, ks, ldb);
#pragma unroll
            for (int i = 0; i < 4; i++) {
                int row = r0 + i * 16;
                uint32_t dd = st + row * ROWB + seg * 16;
                cpa(dd + OFF_A, W + (size_t)row * K   + kg + seg * 8);
                cpa(dd + OFF_B, b + (size_t)row * ldb + ks + seg * 8);
            }
        }
        cpcommit();
    };
    auto issueB = [&](int chunk) {
        const uint32_t st = sb + (chunk & 3) * STAGE;
        const int kg = chunk << 7;
        const hf* b; int ks, ldb;
        bsrc(kg, b, ks, ldb);
#pragma unroll
        for (int i = 0; i < 4; i++) {
            int row = r0 + i * 16;
            cpa(st + row * ROWB + seg * 16 + OFF_B,
                b + (size_t)row * ldb + ks + seg * 8);
        }
        cpcommit();
    };

    if (preA) {
        issueB(0); issueB(1); issueAB(2);
    } else {
        __syncthreads();
        issueAB(0); issueAB(1); issueAB(2);
    }

    const int w = t >> 5, lane = t & 31;
    const int wg = w >> 2, wi = w & 3;
    const int moff = (wi & 1) * 32, noff = (wi >> 1) * 32;
    const int arow = lane & 15, ahalf = lane >> 4;
    const int bj = lane >> 3;
    const int brow = ((bj >> 1) * 8) + (lane & 7), bkh = bj & 1;

#pragma unroll
    for (int mi = 0; mi < 2; mi++)
#pragma unroll
        for (int nj = 0; nj < 4; nj++)
#pragma unroll
            for (int q = 0; q < 4; q++) acc[mi][nj][q] = 0.f;

    for (int s = 0; s < NC; s++) {
        cpwait<2>();
        __syncthreads();
        if ((s & 1) == wg) {
            const uint32_t st = sb + (s & 3) * STAGE;
#pragma unroll
            for (int k16 = 0; k16 < 8; k16++) {
                const int kb = k16 * 32;
                uint32_t ah[2][4], bb[2][4];
#pragma unroll
                for (int mi = 0; mi < 2; mi++) {
                    uint32_t ra = (uint32_t)((moff + mi * 16 + arow) * ROWB + kb + ahalf * 16);
                    LDSM4(ah[mi], st + OFF_A + ra);
                }
#pragma unroll
                for (int ni = 0; ni < 2; ni++) {
                    uint32_t rb = (uint32_t)((noff + ni * 16 + brow) * ROWB + kb + bkh * 16);
                    LDSM4(bb[ni], st + OFF_B + rb);
                }
#pragma unroll
                for (int mi = 0; mi < 2; mi++)
#pragma unroll
                    for (int ni = 0; ni < 2; ni++)
#pragma unroll
                        for (int pp = 0; pp < 2; pp++)
                            MMA(acc[mi][ni * 2 + pp], ah[mi],
                                bb[ni][pp * 2], bb[ni][pp * 2 + 1]);
            }
        }
        if (wflag && s + 3 == xs) {
            if (t == 0)
                while (*(volatile const unsigned*)wflag < wtarget) __nanosleep(64);
            __syncthreads();
        }
        issueAB(s + 3);
    }
}

// merge the two warpgroup partials into cs[64][68] (batch-major)
__device__ __forceinline__ void stage_cs(float acc[2][4][4], float* cs)
{
    const int t = threadIdx.x;
    const int w = t >> 5, lane = t & 31;
    const int wg = w >> 2, wi = w & 3;
    const int moff = (wi & 1) * 32, noff = (wi >> 1) * 32;
    const int rr = lane >> 2, cc = (lane & 3) * 2;
    __syncthreads();
    if (wg == 0) {
#pragma unroll
        for (int mi = 0; mi < 2; mi++)
#pragma unroll
            for (int nj = 0; nj < 4; nj++) {
                int m = moff + mi * 16 + rr;
                int n = noff + nj * 8 + cc;
                cs[n * 68 + m]           = acc[mi][nj][0];
                cs[(n + 1) * 68 + m]     = acc[mi][nj][1];
                cs[n * 68 + m + 8]       = acc[mi][nj][2];
                cs[(n + 1) * 68 + m + 8] = acc[mi][nj][3];
            }
    }
    __syncthreads();
    if (wg == 1) {
#pragma unroll
        for (int mi = 0; mi < 2; mi++)
#pragma unroll
            for (int nj = 0; nj < 4; nj++) {
                int m = moff + mi * 16 + rr;
                int n = noff + nj * 8 + cc;
                cs[n * 68 + m]           += acc[mi][nj][0];
                cs[(n + 1) * 68 + m]     += acc[mi][nj][1];
                cs[n * 68 + m + 8]       += acc[mi][nj][2];
                cs[(n + 1) * 68 + m + 8] += acc[mi][nj][3];
            }
    }
    __syncthreads();
}

__device__ __forceinline__ void barx(unsigned* cnt, unsigned* gen,
                                     unsigned& mygen, unsigned total)
{
    __threadfence();
    __syncthreads();
    if (threadIdx.x == 0) {
        mygen += 1;
        unsigned prev = atomicAdd(cnt, 1u);
        if (prev == total - 1) {
            atomicExch(cnt, 0u);
            __threadfence();
            atomicExch(gen, mygen);
        } else {
            while (atomicAdd(gen, 0u) < mygen) __nanosleep(64);
            __threadfence();
        }
    }
    __syncthreads();
}

// ===========================================================================
// persistent kernels
// ===========================================================================
struct PP {
    const hf *wcat;
    const float *en_b, *de_b;
    hf *hH;
    float *c;
    const hf *fc1w, *fc2w, *fd1w, *fd2w;
    const float *fc1b, *fc2b, *fd1b, *fd2b;
    const hf *xh;
    hf *f1a, *f2a, *d1a;
    float *out;
    unsigned *bar;
    unsigned *arr;
};

__device__ __forceinline__ void lstm_cell_epi(
    float acc[2][4][4], float* cs, const float* bias,
    float* c, hf* hh, int jg0)
{
    stage_cs(acc, cs);
    const int t = threadIdx.x;
    const int b = t >> 2, j4 = (t & 3) * 4;
    float4 cold = *(const float4*)(c + (size_t)b * 2048 + jg0 + j4);
    float cn[4]; hf hi4[4];
#pragma unroll
    for (int q = 0; q < 4; q++) {
        const int j = j4 + q, jg = jg0 + j;
        float iv = cs[b * 68 + j]      + bias[jg];
        float fv = cs[b * 68 + 16 + j] + bias[2048 + jg];
        float gv = cs[b * 68 + 32 + j] + bias[4096 + jg];
        float ov = cs[b * 68 + 48 + j] + bias[6144 + jg];
        float si = 1.f / (1.f + __expf(-iv));
        float sf = 1.f / (1.f + __expf(-fv));
        float so = 1.f / (1.f + __expf(-ov));
        float c2 = sf * (&cold.x)[q] + si * tanhf(gv);
        float h2 = so * tanhf(c2);
        cn[q] = c2;
        hi4[q] = __float2half_rn(h2);
    }
    *(float4*)(c + (size_t)b * 2048 + jg0 + j4) = *(float4*)cn;
    *(uint2*)(hh + (size_t)b * 2048 + jg0 + j4) = *(uint2*)hi4;
}

__device__ __forceinline__ void arrive(unsigned* a)
{
    __syncthreads();
    if (threadIdx.x == 0) { __threadfence(); atomicAdd(a, 1u); }
}

__device__ __forceinline__ void relu_epi(float* cs, const float* bias, int fbase,
                                         hf* outp, int ld)
{
    const int t = threadIdx.x;
    const int b = t >> 2, j0 = (t & 3) * 16;
    const float* bp = bias + fbase + j0;
    hf* dh = outp + (size_t)b * ld + fbase + j0;
#pragma unroll
    for (int j = 0; j < 16; j++) {
        float v = fmaxf(cs[b * 68 + j0 + j] + bp[j], 0.f);
        dh[j] = __float2half_rn(v);
    }
}

__global__ void __launch_bounds__(256)
enc_persist(PP p)
{
    extern __shared__ char smem[];
    const uint32_t sb = (uint32_t)__cvta_generic_to_shared(smem);
    float* cs = (float*)(smem + CS_OFF);
    const int bid = blockIdx.x;
    float acc[2][4][4];
    auto HHp = [&](int l, int pr) { return p.hH + (size_t)(l * 2 + pr) * HB; };

    if (bid < NCTA) {
        const int fbase = bid * TM, jg0 = bid * 16;
        const hf* w0 = p.wcat + (size_t)0 * WCATN + (size_t)fbase * 4096;
        const hf* w1 = p.wcat + (size_t)1 * WCATN + (size_t)fbase * 4096;
        const hf* w2 = p.wcat + (size_t)2 * WCATN + (size_t)fbase * 4096;

        for (int t16 = 0; t16 < 16; t16++) {
            const int rp = t16 & 1, wp = 1 - rp;
            run_gemm(w0, 4096, HHp(0, rp), 2048, 2048,
                     p.f2a + (size_t)t16 * HB, 2048,
                     sb, acc, t16 > 0, p.bar + 6, (unsigned)(t16 + 1));
            gemm_prefA(w1, 4096, sb);
            lstm_cell_epi(acc, cs, p.en_b, p.c, HHp(0, wp), jg0);
            arrive(p.arr + 3 * t16);

            run_gemm(w1, 4096, HHp(1, rp), 2048, 2048, HHp(0, wp), 2048,
                     sb, acc, 1, p.arr + 3 * t16, NCTA);
            gemm_prefA(w2, 4096, sb);
            lstm_cell_epi(acc, cs, p.en_b + 8192, p.c + HB, HHp(1, wp), jg0);
            arrive(p.arr + 3 * t16 + 1);

            run_gemm(w2, 4096, HHp(2, rp), 2048, 2048, HHp(1, wp), 2048,
                     sb, acc, 1, p.arr + 3 * t16 + 1, NCTA);
            if (t16 < 15) gemm_prefA(w0, 4096, sb);
            lstm_cell_epi(acc, cs, p.en_b + 16384, p.c + 2 * HB, HHp(2, wp), jg0);
            arrive(p.arr + 3 * t16 + 2);
        }
    } else {
        const int hbid = bid - NCTA;
        unsigned hgen = 0;
        for (int t16 = 0; t16 < 16; t16++) {
            for (int idx = hbid; idx < 16; idx += NHEAD) {
                const int fbase = idx * TM;
                run_gemm(p.fc1w + (size_t)fbase * 4096, 4096,
                         p.xh + (size_t)t16 * 262144, 4096, 4096,
                         nullptr, 0, sb, acc, 0, nullptr, 0);
                stage_cs(acc, cs);
                relu_epi(cs, p.fc1b, fbase, p.f1a, 1024);
            }
            barx(p.bar + 2, p.bar + 3, hgen, NHEAD);
            for (int idx = hbid; idx < 32; idx += NHEAD) {
                const int fbase = idx * TM;
                run_gemm(p.fc2w + (size_t)fbase * 1024, 1024,
                         p.f1a, 1024, 1024, nullptr, 0, sb, acc, 0, nullptr, 0);
                stage_cs(acc, cs);
                relu_epi(cs, p.fc2b, fbase, p.f2a + (size_t)t16 * HB, 2048);
            }
            barx(p.bar + 2, p.bar + 3, hgen, NHEAD);
            if (hbid == 0 && threadIdx.x == 0)
                atomicExch(p.bar + 6, (unsigned)(t16 + 1));   // f2a(t16) ready
        }
    }
}

__global__ void __launch_bounds__(256)
dec_persist(PP p)
{
    extern __shared__ char smem[];
    const uint32_t sb = (uint32_t)__cvta_generic_to_shared(smem);
    float* cs = (float*)(smem + CS_OFF);
    const int bid = blockIdx.x;
    float acc[2][4][4];
    auto HHp = [&](int l, int pr) { return p.hH + (size_t)(l * 2 + pr) * HB; };

    if (bid < NCTA) {
        const int fbase = bid * TM, jg0 = bid * 16;
        const hf* w0 = p.wcat + (size_t)3 * WCATN + (size_t)fbase * 4096;
        const hf* w1 = p.wcat + (size_t)4 * WCATN + (size_t)fbase * 4096;
        const hf* w2 = p.wcat + (size_t)5 * WCATN + (size_t)fbase * 4096;
        for (int t16 = 0; t16 < 16; t16++) {
            const int rp = t16 & 1, wp = 1 - rp;
            run_gemm(w0, 4096, HHp(0, rp), 2048, 2048, HHp(2, rp), 2048,
                     sb, acc, t16 > 0,
                     t16 > 0 ? p.arr + 3 * t16 - 1 : nullptr, NCTA);
            gemm_prefA(w1, 4096, sb);
            lstm_cell_epi(acc, cs, p.de_b, p.c, HHp(0, wp), jg0);
            arrive(p.arr + 3 * t16);

            run_gemm(w1, 4096, HHp(1, rp), 2048, 2048, HHp(0, wp), 2048,
                     sb, acc, 1, p.arr + 3 * t16, NCTA);
            gemm_prefA(w2, 4096, sb);
            lstm_cell_epi(acc, cs, p.de_b + 8192, p.c + HB, HHp(1, wp), jg0);
            arrive(p.arr + 3 * t16 + 1);

            run_gemm(w2, 4096, HHp(2, rp), 2048, 2048, HHp(1, wp), 2048,
                     sb, acc, 1, p.arr + 3 * t16 + 1, NCTA);
            if (t16 < 15) gemm_prefA(w0, 4096, sb);
            if (t16 >= 2 && threadIdx.x == 0)
                while (*(volatile unsigned*)(p.bar + 5) < (unsigned)(t16 - 1))
                    __nanosleep(64);
            lstm_cell_epi(acc, cs, p.de_b + 16384, p.c + 2 * HB, HHp(2, wp), jg0);
            arrive(p.arr + 3 * t16 + 2);
        }
    } else {
        const int hbid = bid - NCTA;
        unsigned hgen = 0;
        for (int t16 = 0; t16 < 16; t16++) {
            if (threadIdx.x == 0)
                while (*(volatile unsigned*)(p.arr + 3 * t16 + 2) < NCTA)
                    __nanosleep(128);
            __syncthreads();
            __threadfence();
            const int wp = 1 - (t16 & 1);
            if (hbid < 16) {
                const int fbase = hbid * TM;
                run_gemm(p.fd1w + (size_t)fbase * 2048, 2048,
                         HHp(2, wp), 2048, 2048, nullptr, 0,
                         sb, acc, 0, nullptr, 0);
                stage_cs(acc, cs);
                relu_epi(cs, p.fd1b, fbase, p.d1a, 1024);
            }
            barx(p.bar + 2, p.bar + 3, hgen, NHEAD);
            if (hbid == 0 && threadIdx.x == 0)
                atomicExch(p.bar + 5, (unsigned)(t16 + 1));   // h2(t16) consumed
            for (int idx = hbid; idx < 64; idx += NHEAD) {
                const int f2 = idx * TM;
                run_gemm(p.fd2w + (size_t)f2 * 1024, 1024,
                         p.d1a, 1024, 1024, nullptr, 0, sb, acc, 0, nullptr, 0);
                stage_cs(acc, cs);
                const int t = threadIdx.x;
                const int b = t >> 2, j0 = (t & 3) * 16;
                const float* bp = p.fd2b + f2 + j0;
                float* dst = p.out + (size_t)t16 * 262144 + (size_t)b * 4096 + f2 + j0;
#pragma unroll
                for (int j = 0; j < 16; j++) {
                    float v = cs[b * 68 + j0 + j] + bp[j];
                    dst[j] = 1.f / (1.f + __expf(-v));
                }
            }
            barx(p.bar + 2, p.bar + 3, hgen, NHEAD);
        }
    }
}

extern "C" void kernel_launch(void* const* d_in, const int* in_sizes, int n_in,
                              void* d_out, int out_size)
{
    const float* x        = (const float*)d_in[0];
    const float* fc_en1_w = (const float*)d_in[1];
    const float* fc_en1_b = (const float*)d_in[2];
    const float* fc_en2_w = (const float*)d_in[3];
    const float* fc_en2_b = (const float*)d_in[4];
    const float* en_wih   = (const float*)d_in[5];
    const float* en_whh   = (const float*)d_in[6];
    const float* en_b     = (const float*)d_in[7];
    const float* de_wih   = (const float*)d_in[8];
    const float* de_whh   = (const float*)d_in[9];
    const float* de_b     = (const float*)d_in[10];
    const float* fc_de1_w = (const float*)d_in[11];
    const float* fc_de1_b = (const float*)d_in[12];
    const float* fc_de2_w = (const float*)d_in[13];
    const float* fc_de2_b = (const float*)d_in[14];
    float* out = (float*)d_out;

    hf *wcat, *fc1w, *fc2w, *fd1w, *fd2w;
    hf *xh, *f1a, *f2a, *d1a, *hH;
    float *c;
    unsigned *bar, *arr;
    cudaGetSymbolAddress((void**)&wcat, g_wcat);
    cudaGetSymbolAddress((void**)&fc1w, g_fc1w);  cudaGetSymbolAddress((void**)&fc2w, g_fc2w);
    cudaGetSymbolAddress((void**)&fd1w, g_fd1w);  cudaGetSymbolAddress((void**)&fd2w, g_fd2w);
    cudaGetSymbolAddress((void**)&xh, g_xh);
    cudaGetSymbolAddress((void**)&f1a, g_f1a);    cudaGetSymbolAddress((void**)&f2a, g_f2a);
    cudaGetSymbolAddress((void**)&d1a, g_d1a);    cudaGetSymbolAddress((void**)&hH, g_hH);
    cudaGetSymbolAddress((void**)&c, g_c);
    cudaGetSymbolAddress((void**)&bar, g_bar);    cudaGetSymbolAddress((void**)&arr, g_arr);

    cudaFuncSetAttribute(enc_persist, cudaFuncAttributeMaxDynamicSharedMemorySize, SMEM_SZ);
    cudaFuncSetAttribute(dec_persist, cudaFuncAttributeMaxDynamicSharedMemorySize, SMEM_SZ);

    auto HHp = [&](int l, int pr) { return hH + (size_t)(l * 2 + pr) * HB; };

    // ---- prepass: split (FC weights + x) and pack (6 LSTM cat matrices) ----
    {
        SplitArgs a;
        const float* srcs[5] = {fc_en1_w, fc_en2_w, fc_de1_w, fc_de2_w, x};
        hf* hs[5] = {fc1w, fc2w, fd1w, fd2w, xh};
        long ns[5] = {4194304, 2097152, 2097152, 4194304, 4194304};
        long acc = 0;
        for (int i = 0; i < 5; i++) {
            a.s[i] = srcs[i]; a.h[i] = hs[i];
            a.off4[i] = acc; acc += ns[i] / 4;
        }
        a.off4[5] = acc;
        split_all<<<1024, 256>>>(a);
    }
    {
        PackArgs a;
        a.wih[0] = en_wih;                 a.whh[0] = en_whh;
        a.wih[1] = en_wih + (size_t)LWF;   a.whh[1] = en_whh + (size_t)LWF;
        a.wih[2] = en_wih + 2*(size_t)LWF; a.whh[2] = en_whh + 2*(size_t)LWF;
        a.wih[3] = de_wih;                 a.whh[3] = de_whh;
        a.wih[4] = de_wih + (size_t)LWF;   a.whh[4] = de_whh + (size_t)LWF;
        a.wih[5] = de_wih + 2*(size_t)LWF; a.whh[5] = de_whh + 2*(size_t)LWF;
        a.dst = wcat;
        pack_all<<<4096, 256>>>(a);
    }

    cudaMemsetAsync(hH, 0, 6 * HB * sizeof(hf));
    cudaMemsetAsync(c,  0, 3 * HB * sizeof(float));
    cudaMemsetAsync(bar, 0, 8 * sizeof(unsigned));
    cudaMemsetAsync(arr, 0, 64 * sizeof(unsigned));

    PP p;
    p.wcat = wcat;
    p.en_b = en_b; p.de_b = de_b;
    p.hH = hH; p.c = c;
    p.fc1w = fc1w; p.fc2w = fc2w; p.fd1w = fd1w; p.fd2w = fd2w;
    p.fc1b = fc_en1_b; p.fc2b = fc_en2_b; p.fd1b = fc_de1_b; p.fd2b = fc_de2_b;
    p.xh = xh; p.f1a = f1a; p.f2a = f2a; p.d1a = d1a;
    p.out = out; p.bar = bar; p.arr = arr;

    // ---- encoder ----
    enc_persist<<<NCTA + NHEAD, 256, SMEM_SZ>>>(p);

    // ---- decoder init ----
    cudaMemcpyAsync(HHp(0, 0), HHp(2, 0), HB * sizeof(hf), cudaMemcpyDeviceToDevice);
    cudaMemsetAsync(HHp(1, 0), 0, HB * sizeof(hf));
    cudaMemsetAsync(HHp(2, 0), 0, HB * sizeof(hf));
    cudaMemsetAsync(c, 0, 3 * HB * sizeof(float));
    cudaMemsetAsync(bar, 0, 8 * sizeof(unsigned));
    cudaMemsetAsync(arr, 0, 64 * sizeof(unsigned));

    // ---- decoder ----
    dec_persist<<<NCTA + NHEAD, 256, SMEM_SZ>>>(p);
}